// round 15
// baseline (speedup 1.0000x reference)
#include <cuda_runtime.h>
#include <cstdint>
#include <cstddef>

// ---------------- problem constants ----------------
#define BATCH   2
#define SEQ     4096
#define NTOK    (BATCH*SEQ)     // 8192, n = s*BATCH + b
#define DIM     512
#define HEADS   8
#define DHEAD   64
#define FFD     2048
#define VOC     4096
#define NLAYER  6
#define NSPLIT  64
#define SCHUNK  (SEQ / NSPLIT)  // 64
#define QKVD    (3*DIM)         // 1536

// ---------------- scratch (static device allocation only) ----------------
__device__ float g_h   [NTOK*DIM];
__device__ float g_qkv [NTOK*QKVD];
__device__ float g_t   [NTOK*DIM];
__device__ float g_A   [BATCH*HEADS*DHEAD*DHEAD];
__device__ float g_Ap  [NSPLIT*BATCH*HEADS*DHEAD*DHEAD];
__device__ float g_bqkv[NLAYER*QKVD];

// bf16 hi/lo split buffers (packed 2 bf16 per u32)
__device__ uint32_t g_hh[NTOK*DIM/2],  g_hl[NTOK*DIM/2];
__device__ uint32_t g_oh[NTOK*DIM/2],  g_ol[NTOK*DIM/2];
__device__ uint32_t g_fh[NTOK*FFD/2],  g_fl[NTOK*FFD/2];
__device__ uint32_t g_wqkvh[NLAYER*QKVD*DIM/2], g_wqkvl[NLAYER*QKVD*DIM/2];
__device__ uint32_t g_woh[NLAYER*DIM*DIM/2],  g_wol[NLAYER*DIM*DIM/2];
__device__ uint32_t g_w1h[NLAYER*FFD*DIM/2],  g_w1l[NLAYER*FFD*DIM/2];
__device__ uint32_t g_w2h[NLAYER*FFD*DIM/2],  g_w2l[NLAYER*FFD*DIM/2];
__device__ uint32_t g_wfh[VOC*DIM/2],         g_wfl[VOC*DIM/2];

// ================= helpers ==================================================
__device__ __forceinline__ uint32_t smem_u32(const void* p) {
    uint32_t a;
    asm("{ .reg .u64 t; cvta.to.shared.u64 t, %1; cvt.u32.u64 %0, t; }"
        : "=r"(a) : "l"(p));
    return a;
}
__device__ __forceinline__ uint32_t bf16rn(float x) {
    uint32_t u = __float_as_uint(x);
    return (u + 0x7fffu + ((u >> 16) & 1u)) >> 16;
}
__device__ __forceinline__ void cvt_pair(float a, float b, uint32_t& hi, uint32_t& lo) {
    uint32_t ah = bf16rn(a), bh = bf16rn(b);
    float ar = a - __uint_as_float(ah << 16);
    float br = b - __uint_as_float(bh << 16);
    hi = ah | (bh << 16);
    lo = bf16rn(ar) | (bf16rn(br) << 16);
}
__device__ __forceinline__ void ldm4(uint32_t& r0, uint32_t& r1, uint32_t& r2,
                                     uint32_t& r3, uint32_t a) {
    asm volatile("ldmatrix.sync.aligned.m8n8.x4.shared.b16 {%0,%1,%2,%3}, [%4];"
                 : "=r"(r0), "=r"(r1), "=r"(r2), "=r"(r3) : "r"(a));
}
__device__ __forceinline__ void mma16816(float* c,
    uint32_t a0, uint32_t a1, uint32_t a2, uint32_t a3, uint32_t b0, uint32_t b1) {
    asm volatile(
        "mma.sync.aligned.m16n8k16.row.col.f32.bf16.bf16.f32 "
        "{%0,%1,%2,%3}, {%4,%5,%6,%7}, {%8,%9}, {%0,%1,%2,%3};"
        : "+f"(c[0]), "+f"(c[1]), "+f"(c[2]), "+f"(c[3])
        : "r"(a0), "r"(a1), "r"(a2), "r"(a3), "r"(b0), "r"(b1));
}
__device__ __forceinline__ void cp_async16(uint32_t dst, const void* src) {
    asm volatile("cp.async.cg.shared.global [%0], [%1], 16;"
                 :: "r"(dst), "l"(src));
}
__device__ __forceinline__ void cp_commit() {
    asm volatile("cp.async.commit_group;" ::: "memory");
}
template<int N>
__device__ __forceinline__ void cp_wait() {
    asm volatile("cp.async.wait_group %0;" :: "n"(N) : "memory");
}

// ================= tensor-core GEMM (bf16 hi/lo, cp.async 3-stage) ==========
// C[M,Nc] = (Ah+Al)[M,K] @ (Wh+Wl)[Nc,K]^T + bias via Ah*Wh + Ah*Wl + Al*Wh.
// MODE: 1 bias+relu->splits | 2 bias+res(fp32)->fp32 | 3 bias+res(fp32)->fp32+splits
//       4 bias->fp32 transposed [B,V,S] (smem-staged coalesced store)
//       5 bias+per-head norm(seg)->fp32
#define TCM 128
#define TCN 128
#define TCK 32
#define TILE_B 8192               // 128 rows * 64B (swizzled, no pad)
#define OFF_AHI 0
#define OFF_ALO (1*TILE_B)
#define OFF_BHI (2*TILE_B)
#define OFF_BLO (3*TILE_B)
#define STAGE_B (4*TILE_B)        // 32768
#define NSTAGE  3
#define SMEM_GEMM (NSTAGE*STAGE_B) // 98304

__device__ __forceinline__ uint32_t sw_off(uint32_t row, uint32_t c16) {
    return row * 64u + ((c16 ^ (row & 3u) ^ ((row >> 2) & 1u)) * 16u);
}

template<int MODE>
__global__ __launch_bounds__(256, 2) void tc_gemm(
    const uint32_t* __restrict__ Ah, const uint32_t* __restrict__ Al,
    const uint32_t* __restrict__ Wh, const uint32_t* __restrict__ Wl,
    const float* __restrict__ bias, const float* __restrict__ res,
    float* __restrict__ C, uint32_t* __restrict__ Ch, uint32_t* __restrict__ Cl,
    int M, int Nc, int K)
{
    extern __shared__ char smem[];
    const uint32_t sb = smem_u32(smem);
    const int tid  = threadIdx.x, wid = tid >> 5, lane = tid & 31;
    const int bn   = blockIdx.x * TCN, bm = blockIdx.y * TCM;
    const int m0   = (wid & 3) * 32;
    const int n0   = (wid >> 2) * 64;
    const int CCH  = K / TCK;

    const char* pAh = (const char*)Ah;
    const char* pAl = (const char*)Al;
    const char* pWh = (const char*)Wh;
    const char* pWl = (const char*)Wl;

    auto issue_chunk = [&](int c) {
        const uint32_t st = sb + (uint32_t)(c % NSTAGE) * STAGE_B;
        #pragma unroll
        for (int t = 0; t < 2; ++t) {
            const int e   = tid + t * 256;
            const uint32_t row = (uint32_t)(e >> 2);
            const uint32_t c16 = (uint32_t)(e & 3);
            const uint32_t d   = st + sw_off(row, c16);
            const size_t ga = ((size_t)(bm + row) * K + c * TCK) * 2 + c16 * 16u;
            const size_t gb = ((size_t)(bn + row) * K + c * TCK) * 2 + c16 * 16u;
            cp_async16(d + OFF_AHI, pAh + ga);
            cp_async16(d + OFF_ALO, pAl + ga);
            cp_async16(d + OFF_BHI, pWh + gb);
            cp_async16(d + OFF_BLO, pWl + gb);
        }
        cp_commit();
    };

    float acc[2][8][4];
    #pragma unroll
    for (int mi = 0; mi < 2; ++mi)
        #pragma unroll
        for (int ni = 0; ni < 8; ++ni)
            #pragma unroll
            for (int j = 0; j < 4; ++j) acc[mi][ni][j] = 0.f;

    const uint32_t rl   = (uint32_t)(lane & 15);
    const uint32_t cb   = (uint32_t)(lane >> 4);
    const uint32_t x    = (rl & 3u) ^ ((rl >> 2) & 1u);
    const uint32_t rbyt = rl * 64u;
    const uint32_t s0   = ((cb ^ x) * 16u);

    issue_chunk(0);
    issue_chunk(1);

    for (int c = 0; c < CCH; ++c) {
        cp_wait<1>();
        __syncthreads();
        const uint32_t st = sb + (uint32_t)(c % NSTAGE) * STAGE_B;
        const uint32_t aof = st + rbyt + (uint32_t)m0 * 64u;
        const uint32_t bof = st + rbyt + (uint32_t)n0 * 64u;
        #pragma unroll
        for (int kk = 0; kk < 2; ++kk) {
            const uint32_t sl = s0 ^ (kk ? 32u : 0u);
            uint32_t ah[2][4], al[2][4], bh[4][4], bl[4][4];
            ldm4(ah[0][0], ah[0][1], ah[0][2], ah[0][3], aof + OFF_AHI + sl);
            ldm4(ah[1][0], ah[1][1], ah[1][2], ah[1][3], aof + OFF_AHI + 1024u + sl);
            #pragma unroll
            for (int nj = 0; nj < 4; ++nj)
                ldm4(bh[nj][0], bh[nj][1], bh[nj][2], bh[nj][3],
                     bof + OFF_BHI + (uint32_t)nj * 1024u + sl);
            #pragma unroll
            for (int mi = 0; mi < 2; ++mi)
                #pragma unroll
                for (int nj = 0; nj < 4; ++nj) {
                    mma16816(acc[mi][2*nj],   ah[mi][0], ah[mi][1], ah[mi][2], ah[mi][3],
                             bh[nj][0], bh[nj][2]);
                    mma16816(acc[mi][2*nj+1], ah[mi][0], ah[mi][1], ah[mi][2], ah[mi][3],
                             bh[nj][1], bh[nj][3]);
                }
            #pragma unroll
            for (int nj = 0; nj < 4; ++nj)
                ldm4(bl[nj][0], bl[nj][1], bl[nj][2], bl[nj][3],
                     bof + OFF_BLO + (uint32_t)nj * 1024u + sl);
            #pragma unroll
            for (int mi = 0; mi < 2; ++mi)
                #pragma unroll
                for (int nj = 0; nj < 4; ++nj) {
                    mma16816(acc[mi][2*nj],   ah[mi][0], ah[mi][1], ah[mi][2], ah[mi][3],
                             bl[nj][0], bl[nj][2]);
                    mma16816(acc[mi][2*nj+1], ah[mi][0], ah[mi][1], ah[mi][2], ah[mi][3],
                             bl[nj][1], bl[nj][3]);
                }
            ldm4(al[0][0], al[0][1], al[0][2], al[0][3], aof + OFF_ALO + sl);
            ldm4(al[1][0], al[1][1], al[1][2], al[1][3], aof + OFF_ALO + 1024u + sl);
            #pragma unroll
            for (int mi = 0; mi < 2; ++mi)
                #pragma unroll
                for (int nj = 0; nj < 4; ++nj) {
                    mma16816(acc[mi][2*nj],   al[mi][0], al[mi][1], al[mi][2], al[mi][3],
                             bh[nj][0], bh[nj][2]);
                    mma16816(acc[mi][2*nj+1], al[mi][0], al[mi][1], al[mi][2], al[mi][3],
                             bh[nj][1], bh[nj][3]);
                }
        }
        if (c + NSTAGE - 1 < CCH) issue_chunk(c + NSTAGE - 1);
    }

    // ---------------- epilogue ----------------
    const int g = lane >> 2, qq = lane & 3;

    if (MODE == 4) {
        // stage 128x128 fp32 tile in smem (pitch 129 -> conflict-free column
        // reads), then write fully coalesced 256B column runs to out[b][v][s].
        float* stag = (float*)smem;
        __syncthreads();   // all warps done reading stage buffers
        #pragma unroll
        for (int mi = 0; mi < 2; ++mi) {
            const int rloc0 = m0 + mi * 16 + g;
            #pragma unroll
            for (int ni = 0; ni < 8; ++ni) {
                const int cl = n0 + ni * 8 + 2 * qq;
                float2 bb = *(const float2*)&bias[bn + cl];
                stag[rloc0 * 129 + cl]           = acc[mi][ni][0] + bb.x;
                stag[rloc0 * 129 + cl + 1]       = acc[mi][ni][1] + bb.y;
                stag[(rloc0 + 8) * 129 + cl]     = acc[mi][ni][2] + bb.x;
                stag[(rloc0 + 8) * 129 + cl + 1] = acc[mi][ni][3] + bb.y;
            }
        }
        __syncthreads();
        const int sbase = bm >> 1;   // bm even; 64 s-values per b in this tile
        for (int i = tid; i < 128 * 128; i += 256) {
            const int col  = i >> 7;
            const int rem  = i & 127;
            const int b    = rem >> 6;
            const int sidx = rem & 63;
            const int row  = 2 * sidx + b;
            C[((size_t)b * Nc + bn + col) * SEQ + sbase + sidx] =
                stag[row * 129 + col];
        }
        return;
    }

    #pragma unroll
    for (int mi = 0; mi < 2; ++mi) {
        const int r0 = bm + m0 + mi * 16 + g;
        float v[8][4];
        float ss0 = 0.f, ss1 = 0.f;
        #pragma unroll
        for (int ni = 0; ni < 8; ++ni) {
            const int col = bn + n0 + ni * 8 + 2 * qq;
            float2 bb = *(const float2*)&bias[col];
            v[ni][0] = acc[mi][ni][0] + bb.x;
            v[ni][1] = acc[mi][ni][1] + bb.y;
            v[ni][2] = acc[mi][ni][2] + bb.x;
            v[ni][3] = acc[mi][ni][3] + bb.y;
            if (MODE == 5) {
                ss0 += v[ni][0]*v[ni][0] + v[ni][1]*v[ni][1];
                ss1 += v[ni][2]*v[ni][2] + v[ni][3]*v[ni][3];
            }
        }
        if (MODE == 5) {
            const int seg = (bn + n0) >> 9;     // 0=Q(unit) 1=K(unitelu) 2=V(none)
            if (seg < 2) {
                ss0 += __shfl_xor_sync(0xffffffffu, ss0, 1);
                ss0 += __shfl_xor_sync(0xffffffffu, ss0, 2);
                ss1 += __shfl_xor_sync(0xffffffffu, ss1, 1);
                ss1 += __shfl_xor_sync(0xffffffffu, ss1, 2);
                float inv0 = rsqrtf(ss0), inv1 = rsqrtf(ss1);
                #pragma unroll
                for (int ni = 0; ni < 8; ++ni) {
                    v[ni][0] *= inv0; v[ni][1] *= inv0;
                    v[ni][2] *= inv1; v[ni][3] *= inv1;
                    if (seg == 1) {
                        #pragma unroll
                        for (int j = 0; j < 4; ++j)
                            v[ni][j] = v[ni][j] > 0.f ? v[ni][j] : expm1f(v[ni][j]);
                    }
                }
            }
        }
        #pragma unroll
        for (int ni = 0; ni < 8; ++ni) {
            const int col = bn + n0 + ni * 8 + 2 * qq;
            float v0 = v[ni][0], v1 = v[ni][1], v2 = v[ni][2], v3 = v[ni][3];
            if (MODE == 1) {
                v0 = fmaxf(v0, 0.f); v1 = fmaxf(v1, 0.f);
                v2 = fmaxf(v2, 0.f); v3 = fmaxf(v3, 0.f);
            }
            if (MODE == 2 || MODE == 3) {
                float2 r0v = *(const float2*)&res[(size_t)r0 * Nc + col];
                float2 r1v = *(const float2*)&res[(size_t)(r0 + 8) * Nc + col];
                v0 += r0v.x; v1 += r0v.y; v2 += r1v.x; v3 += r1v.y;
            }
            if (MODE == 2 || MODE == 3 || MODE == 5) {
                *(float2*)&C[(size_t)r0 * Nc + col]       = make_float2(v0, v1);
                *(float2*)&C[(size_t)(r0 + 8) * Nc + col] = make_float2(v2, v3);
            }
            if (MODE == 1 || MODE == 3) {
                uint32_t h0, l0, h1, l1;
                cvt_pair(v0, v1, h0, l0);
                cvt_pair(v2, v3, h1, l1);
                size_t i0 = ((size_t)r0 * Nc + col) >> 1;
                size_t i1 = ((size_t)(r0 + 8) * Nc + col) >> 1;
                Ch[i0] = h0; Cl[i0] = l0;
                Ch[i1] = h1; Cl[i1] = l1;
            }
        }
    }
}

// ---------------- fp32 -> bf16 hi/lo split (bulk convert) --------------------
__global__ __launch_bounds__(256) void cvt_split_kernel(
    const float* __restrict__ x, uint32_t* __restrict__ hi,
    uint32_t* __restrict__ lo, int n4)
{
    int i = blockIdx.x * blockDim.x + threadIdx.x;
    if (i >= n4) return;
    float4 v = ((const float4*)x)[i];
    uint32_t h0, l0, h1, l1;
    cvt_pair(v.x, v.y, h0, l0);
    cvt_pair(v.z, v.w, h1, l1);
    ((uint2*)hi)[i] = make_uint2(h0, h1);
    ((uint2*)lo)[i] = make_uint2(l0, l1);
}

// split Wq/Wk/Wv [L][512][512] into wqkv [L][1536][512] slot `which`
__global__ __launch_bounds__(256) void cvt_split_qkv_kernel(
    const float* __restrict__ x, uint32_t* __restrict__ hi,
    uint32_t* __restrict__ lo, int which)
{
    int i = blockIdx.x * blockDim.x + threadIdx.x;
    if (i >= NLAYER*DIM*DIM/4) return;
    float4 v = ((const float4*)x)[i];
    uint32_t h0, l0, h1, l1;
    cvt_pair(v.x, v.y, h0, l0);
    cvt_pair(v.z, v.w, h1, l1);
    int l   = i / (DIM*DIM/4);
    int rem = i % (DIM*DIM/4);
    int row = rem / (DIM/4);
    int c4  = rem % (DIM/4);
    size_t du2 = ((size_t)l*QKVD + which*DIM + row) * (DIM/4) + c4;
    ((uint2*)hi)[du2] = make_uint2(h0, h1);
    ((uint2*)lo)[du2] = make_uint2(l0, l1);
}

__global__ __launch_bounds__(256) void bias_qkv_kernel(
    const float* __restrict__ bq, const float* __restrict__ bk,
    const float* __restrict__ bv, float* __restrict__ bqkv)
{
    int i = blockIdx.x * blockDim.x + threadIdx.x;
    if (i >= NLAYER*QKVD) return;
    int l = i / QKVD, j = i % QKVD;
    float v;
    if (j < DIM)            v = bq[l*DIM + j];
    else if (j < 2*DIM)     v = bk[l*DIM + j - DIM];
    else                    v = bv[l*DIM + j - 2*DIM];
    bqkv[i] = v;
}

// ---------------- embedding (+ split) ----------------------------------------
__global__ __launch_bounds__(256) void embed_kernel(
    const int* __restrict__ input, const float* __restrict__ emb,
    float* __restrict__ h, uint32_t* __restrict__ hh, uint32_t* __restrict__ hl)
{
    int i  = blockIdx.x * blockDim.x + threadIdx.x;
    int n  = i / (DIM/4);
    int c4 = (i % (DIM/4)) * 4;
    int s  = n >> 1, b = n & 1;
    int tok = input[b*SEQ + s];
    float4 v = *(const float4*)&emb[(size_t)tok*DIM + c4];
    *(float4*)&h[(size_t)n*DIM + c4] = v;
    uint32_t h0, l0, h1, l1;
    cvt_pair(v.x, v.y, h0, l0);
    cvt_pair(v.z, v.w, h1, l1);
    size_t o = ((size_t)n*DIM + c4) >> 1;
    hh[o] = h0; hh[o+1] = h1;
    hl[o] = l0; hl[o+1] = l1;
}

// ---------- A_part[sp,b,h,dv,dq] = sum_{s in chunk} v[s,dv] * k[s,dq] ---------
__global__ __launch_bounds__(256) void attnA_kernel(
    const float* __restrict__ qkv, float* __restrict__ Apart)
{
    int bh = blockIdx.x;
    int sp = blockIdx.y;
    int b  = bh / HEADS, h = bh % HEADS;
    __shared__ float ks[16][64], vs[16][64];
    int tid = threadIdx.x;
    int dq  = tid & 63;
    int dvb = (tid >> 6) * 16;
    float acc[16];
    #pragma unroll
    for (int j = 0; j < 16; ++j) acc[j] = 0.f;

    int s0 = sp * SCHUNK;
    int r  = tid >> 4;
    int c  = (tid & 15) * 4;
    for (int st = 0; st < SCHUNK; st += 16) {
        int s = s0 + st + r;
        size_t base = ((size_t)(s*BATCH + b))*QKVD + h*DHEAD + c;
        *(float4*)&ks[r][c] = *(const float4*)&qkv[base + DIM];
        *(float4*)&vs[r][c] = *(const float4*)&qkv[base + 2*DIM];
        __syncthreads();
        #pragma unroll
        for (int ss = 0; ss < 16; ++ss) {
            float kq = ks[ss][dq];
            #pragma unroll
            for (int j = 0; j < 16; ++j)
                acc[j] = fmaf(vs[ss][dvb+j], kq, acc[j]);
        }
        __syncthreads();
    }
    float* out = Apart + ((size_t)sp*(BATCH*HEADS) + bh)*DHEAD*DHEAD;
    #pragma unroll
    for (int j = 0; j < 16; ++j) out[(dvb+j)*DHEAD + dq] = acc[j];
}

__global__ __launch_bounds__(256) void areduce_kernel(
    const float* __restrict__ Apart, float* __restrict__ Aout)
{
    int i = blockIdx.x * blockDim.x + threadIdx.x;
    float sum = 0.f;
    #pragma unroll 8
    for (int sp = 0; sp < NSPLIT; ++sp)
        sum += Apart[(size_t)sp*(BATCH*HEADS*DHEAD*DHEAD) + i];
    Aout[i] = sum;
}

// ---------- o = q . A  -> bf16 hi/lo split output -----------------------------
__global__ __launch_bounds__(256) void attnO_kernel(
    const float* __restrict__ qkv, const float* __restrict__ A,
    uint32_t* __restrict__ oh, uint32_t* __restrict__ ol)
{
    int h  = blockIdx.x, b = blockIdx.y;
    int s0 = blockIdx.z * 64;
    __shared__ float Asm[64][65];
    __shared__ float qs[64][64];
    int tid = threadIdx.x;
    const float* Ab = A + ((size_t)(b*HEADS + h))*DHEAD*DHEAD;
    for (int i = tid; i < 4096; i += 256) Asm[i >> 6][i & 63] = Ab[i];

    int r = tid >> 2;
    int c = (tid & 3) * 16;
    size_t qbase = ((size_t)((s0 + r)*BATCH + b))*QKVD + h*DHEAD + c;
    #pragma unroll
    for (int u = 0; u < 4; ++u)
        *(float4*)&qs[r][c + u*4] = *(const float4*)&qkv[qbase + u*4];
    __syncthreads();

    int dv2 = (tid & 31) * 2;
    int rb  = (tid >> 5) * 8;
    for (int rr = 0; rr < 8; ++rr) {
        float a0 = 0.f, a1 = 0.f;
        #pragma unroll
        for (int dq = 0; dq < 64; ++dq) {
            float qv = qs[rb+rr][dq];
            a0 = fmaf(qv, Asm[dv2][dq],   a0);
            a1 = fmaf(qv, Asm[dv2+1][dq], a1);
        }
        int s = s0 + rb + rr;
        uint32_t hh, ll;
        cvt_pair(a0, a1, hh, ll);
        size_t idx = (((size_t)(s*BATCH + b))*DIM + h*DHEAD + dv2) >> 1;
        oh[idx] = hh; ol[idx] = ll;
    }
}

// ---------------- layernorm (+ split output) ----------------------------------
__global__ __launch_bounds__(256) void ln_kernel(
    const float* __restrict__ x, const float* __restrict__ g,
    const float* __restrict__ be, float* __restrict__ out,
    uint32_t* __restrict__ oh, uint32_t* __restrict__ ol)
{
    __shared__ float s1[8], s2[8];
    int n = blockIdx.x, tid = threadIdx.x;
    const float* xr = x + (size_t)n*DIM;
    float2 v = *(const float2*)(xr + tid*2);
    float s = v.x + v.y, sq = v.x*v.x + v.y*v.y;
    #pragma unroll
    for (int o = 16; o; o >>= 1) {
        s  += __shfl_xor_sync(0xffffffffu, s , o);
        sq += __shfl_xor_sync(0xffffffffu, sq, o);
    }
    if ((tid & 31) == 0) { s1[tid>>5] = s; s2[tid>>5] = sq; }
    __syncthreads();
    if (tid < 32) {
        s  = (tid < 8) ? s1[tid] : 0.f;
        sq = (tid < 8) ? s2[tid] : 0.f;
        #pragma unroll
        for (int o = 4; o; o >>= 1) {
            s  += __shfl_xor_sync(0xffffffffu, s , o);
            sq += __shfl_xor_sync(0xffffffffu, sq, o);
        }
        if (tid == 0) { s1[0] = s; s2[0] = sq; }
    }
    __syncthreads();
    float mean = s1[0] * (1.0f/DIM);
    float var  = s2[0] * (1.0f/DIM) - mean*mean;
    float inv  = rsqrtf(var + 1e-5f);
    float2 gg = *(const float2*)(g  + tid*2);
    float2 bb = *(const float2*)(be + tid*2);
    float rx = (v.x - mean)*inv*gg.x + bb.x;
    float ry = (v.y - mean)*inv*gg.y + bb.y;
    *(float2*)(out + (size_t)n*DIM + tid*2) = make_float2(rx, ry);
    uint32_t hh, ll;
    cvt_pair(rx, ry, hh, ll);
    oh[(size_t)n*(DIM/2) + tid] = hh;
    ol[(size_t)n*(DIM/2) + tid] = ll;
}

// ---------------- orchestration ----------------------------------------------
extern "C" void kernel_launch(void* const* d_in, const int* in_sizes, int n_in,
                              void* d_out, int out_size)
{
    (void)in_sizes; (void)n_in; (void)out_size;
    const int*   input = (const int*)  d_in[0];
    const float* emb   = (const float*)d_in[1];
    const float* Wq    = (const float*)d_in[2];
    const float* bq    = (const float*)d_in[3];
    const float* Wk    = (const float*)d_in[4];
    const float* bk    = (const float*)d_in[5];
    const float* Wv    = (const float*)d_in[6];
    const float* bv    = (const float*)d_in[7];
    const float* Wo    = (const float*)d_in[8];
    const float* bo    = (const float*)d_in[9];
    const float* W1    = (const float*)d_in[10];
    const float* b1    = (const float*)d_in[11];
    const float* W2    = (const float*)d_in[12];
    const float* b2    = (const float*)d_in[13];
    const float* g2    = (const float*)d_in[14];
    const float* be2   = (const float*)d_in[15];
    const float* Wfc   = (const float*)d_in[16];
    const float* bfc   = (const float*)d_in[17];

    float *h, *qkv, *tb, *Ab, *Apb, *bqkv;
    uint32_t *hh, *hl, *oh, *ol, *fh, *fl;
    uint32_t *wqkvh, *wqkvl, *woh, *wol, *w1h, *w1l, *w2h, *w2l, *wfh, *wfl;
    cudaGetSymbolAddress((void**)&h,    g_h);
    cudaGetSymbolAddress((void**)&qkv,  g_qkv);
    cudaGetSymbolAddress((void**)&tb,   g_t);
    cudaGetSymbolAddress((void**)&Ab,   g_A);
    cudaGetSymbolAddress((void**)&Apb,  g_Ap);
    cudaGetSymbolAddress((void**)&bqkv, g_bqkv);
    cudaGetSymbolAddress((void**)&hh,  g_hh);  cudaGetSymbolAddress((void**)&hl, g_hl);
    cudaGetSymbolAddress((void**)&oh,  g_oh);  cudaGetSymbolAddress((void**)&ol, g_ol);
    cudaGetSymbolAddress((void**)&fh,  g_fh);  cudaGetSymbolAddress((void**)&fl, g_fl);
    cudaGetSymbolAddress((void**)&wqkvh, g_wqkvh); cudaGetSymbolAddress((void**)&wqkvl, g_wqkvl);
    cudaGetSymbolAddress((void**)&woh, g_woh); cudaGetSymbolAddress((void**)&wol, g_wol);
    cudaGetSymbolAddress((void**)&w1h, g_w1h); cudaGetSymbolAddress((void**)&w1l, g_w1l);
    cudaGetSymbolAddress((void**)&w2h, g_w2h); cudaGetSymbolAddress((void**)&w2l, g_w2l);
    cudaGetSymbolAddress((void**)&wfh, g_wfh); cudaGetSymbolAddress((void**)&wfl, g_wfl);

    cudaFuncSetAttribute(tc_gemm<1>, cudaFuncAttributeMaxDynamicSharedMemorySize, SMEM_GEMM);
    cudaFuncSetAttribute(tc_gemm<2>, cudaFuncAttributeMaxDynamicSharedMemorySize, SMEM_GEMM);
    cudaFuncSetAttribute(tc_gemm<3>, cudaFuncAttributeMaxDynamicSharedMemorySize, SMEM_GEMM);
    cudaFuncSetAttribute(tc_gemm<4>, cudaFuncAttributeMaxDynamicSharedMemorySize, SMEM_GEMM);
    cudaFuncSetAttribute(tc_gemm<5>, cudaFuncAttributeMaxDynamicSharedMemorySize, SMEM_GEMM);

    const dim3 gQKV(QKVD/TCN, NTOK/TCM);   // (12, 64)
    const dim3 gD  (DIM/TCN,  NTOK/TCM);   // (4, 64)
    const dim3 gFF (FFD/TCN,  NTOK/TCM);   // (16, 64)
    const dim3 gV  (VOC/TCN,  NTOK/TCM);   // (32, 64)

    // --- prologue ordered so launch #5 (0-based) is the first tc_gemm:
    //     0..2 = QKV weight splits, 3 = bias concat, 4 = embed, 5 = QKV GEMM.
    //     Remaining weight splits follow; stream order still puts them before
    //     their first consumer (Wo-GEMM).
    {
        int nD = NLAYER*DIM*DIM/4, nF = NLAYER*FFD*DIM/4, nV = VOC*DIM/4;
        cvt_split_qkv_kernel<<<(nD+255)/256, 256>>>(Wq, wqkvh, wqkvl, 0);
        cvt_split_qkv_kernel<<<(nD+255)/256, 256>>>(Wk, wqkvh, wqkvl, 1);
        cvt_split_qkv_kernel<<<(nD+255)/256, 256>>>(Wv, wqkvh, wqkvl, 2);
        bias_qkv_kernel<<<(NLAYER*QKVD+255)/256, 256>>>(bq, bk, bv, bqkv);
        embed_kernel<<<(NTOK*DIM/4)/256, 256>>>(input, emb, h, hh, hl);

        // layer 0 QKV GEMM — launch index 5, captured by ncu (-s 5 -c 1)
        tc_gemm<5><<<gQKV, 256, SMEM_GEMM>>>(hh, hl, wqkvh, wqkvl,
                                             bqkv, nullptr,
                                             qkv, nullptr, nullptr, NTOK, QKVD, DIM);

        cvt_split_kernel<<<(nD+255)/256, 256>>>(Wo, woh, wol, nD);
        cvt_split_kernel<<<(nF+255)/256, 256>>>(W1, w1h, w1l, nF);
        cvt_split_kernel<<<(nF+255)/256, 256>>>(W2, w2h, w2l, nF);
        cvt_split_kernel<<<(nV+255)/256, 256>>>(Wfc, wfh, wfl, nV);
    }

    for (int l = 0; l < NLAYER; ++l) {
        const size_t oQ = (size_t)l*QKVD*DIM/2;
        const size_t oD = (size_t)l*DIM*DIM/2;
        const size_t oF = (size_t)l*FFD*DIM/2;
        const float* bol = bo + l*DIM;
        const float* b1l = b1 + l*FFD;
        const float* b2l = b2 + l*DIM;
        const float* g2l = g2 + l*DIM;
        const float* be2l= be2+ l*DIM;

        // QKV = h @ [Wq;Wk;Wv]^T + bias, fused unit/unitelu per segment
        // (layer 0's QKV GEMM already launched in the prologue)
        if (l > 0)
            tc_gemm<5><<<gQKV, 256, SMEM_GEMM>>>(hh, hl, wqkvh+oQ, wqkvl+oQ,
                                                 bqkv + l*QKVD, nullptr,
                                                 qkv, nullptr, nullptr, NTOK, QKVD, DIM);
        attnA_kernel<<<dim3(BATCH*HEADS, NSPLIT), 256>>>(qkv, Apb);
        areduce_kernel<<<(BATCH*HEADS*DHEAD*DHEAD)/256, 256>>>(Apb, Ab);
        attnO_kernel<<<dim3(HEADS, BATCH, SEQ/64), 256>>>(qkv, Ab, oh, ol);
        // h = h + o Wo^T + bo  (fp32 residual, writes fp32 h + splits)
        tc_gemm<3><<<gD, 256, SMEM_GEMM>>>(oh, ol, woh+oD, wol+oD, bol, h,
                                           h, hh, hl, NTOK, DIM, DIM);
        // f = relu(h W1^T + b1)  (splits)
        tc_gemm<1><<<gFF, 256, SMEM_GEMM>>>(hh, hl, w1h+oF, w1l+oF, b1l, nullptr,
                                            nullptr, fh, fl, NTOK, FFD, DIM);
        // t = h + f W2^T + b2  (fp32 residual, fp32 out for LN)
        tc_gemm<2><<<gD, 256, SMEM_GEMM>>>(fh, fl, w2h+oF, w2l+oF, b2l, h,
                                           tb, nullptr, nullptr, NTOK, DIM, FFD);
        // h = LN(t)  (fp32 h + splits)
        ln_kernel<<<NTOK, 256>>>(tb, g2l, be2l, h, hh, hl);
    }

    // logits, written directly transposed into d_out [B, V, S]
    tc_gemm<4><<<gV, 256, SMEM_GEMM>>>(hh, hl, wfh, wfl, bfc, nullptr,
                                       (float*)d_out, nullptr, nullptr, NTOK, VOC, DIM);
}

// round 16
// speedup vs baseline: 1.0044x; 1.0044x over previous
#include <cuda_runtime.h>
#include <cstdint>
#include <cstddef>

// ---------------- problem constants ----------------
#define BATCH   2
#define SEQ     4096
#define NTOK    (BATCH*SEQ)     // 8192, n = s*BATCH + b
#define DIM     512
#define HEADS   8
#define DHEAD   64
#define FFD     2048
#define VOC     4096
#define NLAYER  6
#define NSPLIT  64
#define SCHUNK  (SEQ / NSPLIT)  // 64
#define QKVD    (3*DIM)         // 1536

// ---------------- scratch (static device allocation only) ----------------
__device__ float g_h   [NTOK*DIM];
__device__ float g_qkv [NTOK*QKVD];
__device__ float g_t   [NTOK*DIM];
__device__ float g_A   [BATCH*HEADS*DHEAD*DHEAD];
__device__ float g_Ap  [NSPLIT*BATCH*HEADS*DHEAD*DHEAD];
__device__ float g_bqkv[NLAYER*QKVD];

// bf16 hi/lo split buffers (packed 2 bf16 per u32)
__device__ uint32_t g_hh[NTOK*DIM/2],  g_hl[NTOK*DIM/2];
__device__ uint32_t g_oh[NTOK*DIM/2],  g_ol[NTOK*DIM/2];
__device__ uint32_t g_fh[NTOK*FFD/2],  g_fl[NTOK*FFD/2];
__device__ uint32_t g_wqkvh[NLAYER*QKVD*DIM/2], g_wqkvl[NLAYER*QKVD*DIM/2];
__device__ uint32_t g_woh[NLAYER*DIM*DIM/2],  g_wol[NLAYER*DIM*DIM/2];
__device__ uint32_t g_w1h[NLAYER*FFD*DIM/2],  g_w1l[NLAYER*FFD*DIM/2];
__device__ uint32_t g_w2h[NLAYER*FFD*DIM/2],  g_w2l[NLAYER*FFD*DIM/2];
__device__ uint32_t g_wfh[VOC*DIM/2],         g_wfl[VOC*DIM/2];

// ================= helpers ==================================================
__device__ __forceinline__ uint32_t smem_u32(const void* p) {
    uint32_t a;
    asm("{ .reg .u64 t; cvta.to.shared.u64 t, %1; cvt.u32.u64 %0, t; }"
        : "=r"(a) : "l"(p));
    return a;
}
__device__ __forceinline__ uint32_t bf16rn(float x) {
    uint32_t u = __float_as_uint(x);
    return (u + 0x7fffu + ((u >> 16) & 1u)) >> 16;
}
__device__ __forceinline__ void cvt_pair(float a, float b, uint32_t& hi, uint32_t& lo) {
    uint32_t ah = bf16rn(a), bh = bf16rn(b);
    float ar = a - __uint_as_float(ah << 16);
    float br = b - __uint_as_float(bh << 16);
    hi = ah | (bh << 16);
    lo = bf16rn(ar) | (bf16rn(br) << 16);
}
__device__ __forceinline__ void ldm4(uint32_t& r0, uint32_t& r1, uint32_t& r2,
                                     uint32_t& r3, uint32_t a) {
    asm volatile("ldmatrix.sync.aligned.m8n8.x4.shared.b16 {%0,%1,%2,%3}, [%4];"
                 : "=r"(r0), "=r"(r1), "=r"(r2), "=r"(r3) : "r"(a));
}
__device__ __forceinline__ void mma16816(float* c,
    uint32_t a0, uint32_t a1, uint32_t a2, uint32_t a3, uint32_t b0, uint32_t b1) {
    asm volatile(
        "mma.sync.aligned.m16n8k16.row.col.f32.bf16.bf16.f32 "
        "{%0,%1,%2,%3}, {%4,%5,%6,%7}, {%8,%9}, {%0,%1,%2,%3};"
        : "+f"(c[0]), "+f"(c[1]), "+f"(c[2]), "+f"(c[3])
        : "r"(a0), "r"(a1), "r"(a2), "r"(a3), "r"(b0), "r"(b1));
}
__device__ __forceinline__ void cp_async16(uint32_t dst, const void* src) {
    asm volatile("cp.async.cg.shared.global [%0], [%1], 16;"
                 :: "r"(dst), "l"(src));
}
__device__ __forceinline__ void cp_commit() {
    asm volatile("cp.async.commit_group;" ::: "memory");
}
template<int N>
__device__ __forceinline__ void cp_wait() {
    asm volatile("cp.async.wait_group %0;" :: "n"(N) : "memory");
}

// ================= tensor-core GEMM (bf16 hi/lo, cp.async 3-stage) ==========
// C[M,Nc] = (Ah+Al)[M,K] @ (Wh+Wl)[Nc,K]^T + bias via Ah*Wh + Ah*Wl + Al*Wh.
// MODE: 1 bias+relu->splits | 2 bias+res(fp32)->fp32 | 3 bias+res(fp32)->fp32+splits
//       4 bias->fp32 transposed [B,V,S] (smem-staged coalesced store)
//       5 bias+per-head norm(seg)->fp32
#define TCM 128
#define TCN 128
#define TCK 32
#define TILE_B 8192               // 128 rows * 64B (swizzled, no pad)
#define OFF_AHI 0
#define OFF_ALO (1*TILE_B)
#define OFF_BHI (2*TILE_B)
#define OFF_BLO (3*TILE_B)
#define STAGE_B (4*TILE_B)        // 32768
#define NSTAGE  3
#define SMEM_GEMM (NSTAGE*STAGE_B) // 98304

__device__ __forceinline__ uint32_t sw_off(uint32_t row, uint32_t c16) {
    return row * 64u + ((c16 ^ (row & 3u) ^ ((row >> 2) & 1u)) * 16u);
}

template<int MODE>
__global__ __launch_bounds__(256, 2) void tc_gemm(
    const uint32_t* __restrict__ Ah, const uint32_t* __restrict__ Al,
    const uint32_t* __restrict__ Wh, const uint32_t* __restrict__ Wl,
    const float* __restrict__ bias, const float* __restrict__ res,
    float* __restrict__ C, uint32_t* __restrict__ Ch, uint32_t* __restrict__ Cl,
    int M, int Nc, int K)
{
    extern __shared__ char smem[];
    const uint32_t sb = smem_u32(smem);
    const int tid  = threadIdx.x, wid = tid >> 5, lane = tid & 31;
    const int bn   = blockIdx.x * TCN, bm = blockIdx.y * TCM;
    const int m0   = (wid & 3) * 32;
    const int n0   = (wid >> 2) * 64;
    const int CCH  = K / TCK;

    const char* pAh = (const char*)Ah;
    const char* pAl = (const char*)Al;
    const char* pWh = (const char*)Wh;
    const char* pWl = (const char*)Wl;

    auto issue_chunk = [&](int c) {
        const uint32_t st = sb + (uint32_t)(c % NSTAGE) * STAGE_B;
        #pragma unroll
        for (int t = 0; t < 2; ++t) {
            const int e   = tid + t * 256;
            const uint32_t row = (uint32_t)(e >> 2);
            const uint32_t c16 = (uint32_t)(e & 3);
            const uint32_t d   = st + sw_off(row, c16);
            const size_t ga = ((size_t)(bm + row) * K + c * TCK) * 2 + c16 * 16u;
            const size_t gb = ((size_t)(bn + row) * K + c * TCK) * 2 + c16 * 16u;
            cp_async16(d + OFF_AHI, pAh + ga);
            cp_async16(d + OFF_ALO, pAl + ga);
            cp_async16(d + OFF_BHI, pWh + gb);
            cp_async16(d + OFF_BLO, pWl + gb);
        }
        cp_commit();
    };

    float acc[2][8][4];
    #pragma unroll
    for (int mi = 0; mi < 2; ++mi)
        #pragma unroll
        for (int ni = 0; ni < 8; ++ni)
            #pragma unroll
            for (int j = 0; j < 4; ++j) acc[mi][ni][j] = 0.f;

    const uint32_t rl   = (uint32_t)(lane & 15);
    const uint32_t cb   = (uint32_t)(lane >> 4);
    const uint32_t x    = (rl & 3u) ^ ((rl >> 2) & 1u);
    const uint32_t rbyt = rl * 64u;
    const uint32_t s0   = ((cb ^ x) * 16u);

    issue_chunk(0);
    issue_chunk(1);

    for (int c = 0; c < CCH; ++c) {
        cp_wait<1>();
        __syncthreads();
        const uint32_t st = sb + (uint32_t)(c % NSTAGE) * STAGE_B;
        const uint32_t aof = st + rbyt + (uint32_t)m0 * 64u;
        const uint32_t bof = st + rbyt + (uint32_t)n0 * 64u;
        #pragma unroll
        for (int kk = 0; kk < 2; ++kk) {
            const uint32_t sl = s0 ^ (kk ? 32u : 0u);
            uint32_t ah[2][4], al[2][4], bh[4][4], bl[4][4];
            ldm4(ah[0][0], ah[0][1], ah[0][2], ah[0][3], aof + OFF_AHI + sl);
            ldm4(ah[1][0], ah[1][1], ah[1][2], ah[1][3], aof + OFF_AHI + 1024u + sl);
            #pragma unroll
            for (int nj = 0; nj < 4; ++nj)
                ldm4(bh[nj][0], bh[nj][1], bh[nj][2], bh[nj][3],
                     bof + OFF_BHI + (uint32_t)nj * 1024u + sl);
            #pragma unroll
            for (int mi = 0; mi < 2; ++mi)
                #pragma unroll
                for (int nj = 0; nj < 4; ++nj) {
                    mma16816(acc[mi][2*nj],   ah[mi][0], ah[mi][1], ah[mi][2], ah[mi][3],
                             bh[nj][0], bh[nj][2]);
                    mma16816(acc[mi][2*nj+1], ah[mi][0], ah[mi][1], ah[mi][2], ah[mi][3],
                             bh[nj][1], bh[nj][3]);
                }
            #pragma unroll
            for (int nj = 0; nj < 4; ++nj)
                ldm4(bl[nj][0], bl[nj][1], bl[nj][2], bl[nj][3],
                     bof + OFF_BLO + (uint32_t)nj * 1024u + sl);
            #pragma unroll
            for (int mi = 0; mi < 2; ++mi)
                #pragma unroll
                for (int nj = 0; nj < 4; ++nj) {
                    mma16816(acc[mi][2*nj],   ah[mi][0], ah[mi][1], ah[mi][2], ah[mi][3],
                             bl[nj][0], bl[nj][2]);
                    mma16816(acc[mi][2*nj+1], ah[mi][0], ah[mi][1], ah[mi][2], ah[mi][3],
                             bl[nj][1], bl[nj][3]);
                }
            ldm4(al[0][0], al[0][1], al[0][2], al[0][3], aof + OFF_ALO + sl);
            ldm4(al[1][0], al[1][1], al[1][2], al[1][3], aof + OFF_ALO + 1024u + sl);
            #pragma unroll
            for (int mi = 0; mi < 2; ++mi)
                #pragma unroll
                for (int nj = 0; nj < 4; ++nj) {
                    mma16816(acc[mi][2*nj],   al[mi][0], al[mi][1], al[mi][2], al[mi][3],
                             bh[nj][0], bh[nj][2]);
                    mma16816(acc[mi][2*nj+1], al[mi][0], al[mi][1], al[mi][2], al[mi][3],
                             bh[nj][1], bh[nj][3]);
                }
        }
        if (c + NSTAGE - 1 < CCH) issue_chunk(c + NSTAGE - 1);
    }

    // ---------------- epilogue ----------------
    const int g = lane >> 2, qq = lane & 3;

    if (MODE == 4) {
        // stage 128x128 fp32 tile in smem (pitch 129 -> conflict-free column
        // reads), then write fully coalesced 256B column runs to out[b][v][s].
        float* stag = (float*)smem;
        __syncthreads();   // all warps done reading stage buffers
        #pragma unroll
        for (int mi = 0; mi < 2; ++mi) {
            const int rloc0 = m0 + mi * 16 + g;
            #pragma unroll
            for (int ni = 0; ni < 8; ++ni) {
                const int cl = n0 + ni * 8 + 2 * qq;
                float2 bb = *(const float2*)&bias[bn + cl];
                stag[rloc0 * 129 + cl]           = acc[mi][ni][0] + bb.x;
                stag[rloc0 * 129 + cl + 1]       = acc[mi][ni][1] + bb.y;
                stag[(rloc0 + 8) * 129 + cl]     = acc[mi][ni][2] + bb.x;
                stag[(rloc0 + 8) * 129 + cl + 1] = acc[mi][ni][3] + bb.y;
            }
        }
        __syncthreads();
        const int sbase = bm >> 1;   // bm even; 64 s-values per b in this tile
        for (int i = tid; i < 128 * 128; i += 256) {
            const int col  = i >> 7;
            const int rem  = i & 127;
            const int b    = rem >> 6;
            const int sidx = rem & 63;
            const int row  = 2 * sidx + b;
            C[((size_t)b * Nc + bn + col) * SEQ + sbase + sidx] =
                stag[row * 129 + col];
        }
        return;
    }

    #pragma unroll
    for (int mi = 0; mi < 2; ++mi) {
        const int r0 = bm + m0 + mi * 16 + g;
        float v[8][4];
        float ss0 = 0.f, ss1 = 0.f;
        #pragma unroll
        for (int ni = 0; ni < 8; ++ni) {
            const int col = bn + n0 + ni * 8 + 2 * qq;
            float2 bb = *(const float2*)&bias[col];
            v[ni][0] = acc[mi][ni][0] + bb.x;
            v[ni][1] = acc[mi][ni][1] + bb.y;
            v[ni][2] = acc[mi][ni][2] + bb.x;
            v[ni][3] = acc[mi][ni][3] + bb.y;
            if (MODE == 5) {
                ss0 += v[ni][0]*v[ni][0] + v[ni][1]*v[ni][1];
                ss1 += v[ni][2]*v[ni][2] + v[ni][3]*v[ni][3];
            }
        }
        if (MODE == 5) {
            const int seg = (bn + n0) >> 9;     // 0=Q(unit) 1=K(unitelu) 2=V(none)
            if (seg < 2) {
                ss0 += __shfl_xor_sync(0xffffffffu, ss0, 1);
                ss0 += __shfl_xor_sync(0xffffffffu, ss0, 2);
                ss1 += __shfl_xor_sync(0xffffffffu, ss1, 1);
                ss1 += __shfl_xor_sync(0xffffffffu, ss1, 2);
                float inv0 = rsqrtf(ss0), inv1 = rsqrtf(ss1);
                #pragma unroll
                for (int ni = 0; ni < 8; ++ni) {
                    v[ni][0] *= inv0; v[ni][1] *= inv0;
                    v[ni][2] *= inv1; v[ni][3] *= inv1;
                    if (seg == 1) {
                        #pragma unroll
                        for (int j = 0; j < 4; ++j)
                            v[ni][j] = v[ni][j] > 0.f ? v[ni][j] : expm1f(v[ni][j]);
                    }
                }
            }
        }
        #pragma unroll
        for (int ni = 0; ni < 8; ++ni) {
            const int col = bn + n0 + ni * 8 + 2 * qq;
            float v0 = v[ni][0], v1 = v[ni][1], v2 = v[ni][2], v3 = v[ni][3];
            if (MODE == 1) {
                v0 = fmaxf(v0, 0.f); v1 = fmaxf(v1, 0.f);
                v2 = fmaxf(v2, 0.f); v3 = fmaxf(v3, 0.f);
            }
            if (MODE == 2 || MODE == 3) {
                float2 r0v = *(const float2*)&res[(size_t)r0 * Nc + col];
                float2 r1v = *(const float2*)&res[(size_t)(r0 + 8) * Nc + col];
                v0 += r0v.x; v1 += r0v.y; v2 += r1v.x; v3 += r1v.y;
            }
            if (MODE == 2 || MODE == 3 || MODE == 5) {
                *(float2*)&C[(size_t)r0 * Nc + col]       = make_float2(v0, v1);
                *(float2*)&C[(size_t)(r0 + 8) * Nc + col] = make_float2(v2, v3);
            }
            if (MODE == 1 || MODE == 3) {
                uint32_t h0, l0, h1, l1;
                cvt_pair(v0, v1, h0, l0);
                cvt_pair(v2, v3, h1, l1);
                size_t i0 = ((size_t)r0 * Nc + col) >> 1;
                size_t i1 = ((size_t)(r0 + 8) * Nc + col) >> 1;
                Ch[i0] = h0; Cl[i0] = l0;
                Ch[i1] = h1; Cl[i1] = l1;
            }
        }
    }
}

// ---------------- fp32 -> bf16 hi/lo split (bulk convert) --------------------
__global__ __launch_bounds__(256) void cvt_split_kernel(
    const float* __restrict__ x, uint32_t* __restrict__ hi,
    uint32_t* __restrict__ lo, int n4)
{
    int i = blockIdx.x * blockDim.x + threadIdx.x;
    if (i >= n4) return;
    float4 v = ((const float4*)x)[i];
    uint32_t h0, l0, h1, l1;
    cvt_pair(v.x, v.y, h0, l0);
    cvt_pair(v.z, v.w, h1, l1);
    ((uint2*)hi)[i] = make_uint2(h0, h1);
    ((uint2*)lo)[i] = make_uint2(l0, l1);
}

// split Wq/Wk/Wv [L][512][512] into wqkv [L][1536][512] slot `which`
__global__ __launch_bounds__(256) void cvt_split_qkv_kernel(
    const float* __restrict__ x, uint32_t* __restrict__ hi,
    uint32_t* __restrict__ lo, int which)
{
    int i = blockIdx.x * blockDim.x + threadIdx.x;
    if (i >= NLAYER*DIM*DIM/4) return;
    float4 v = ((const float4*)x)[i];
    uint32_t h0, l0, h1, l1;
    cvt_pair(v.x, v.y, h0, l0);
    cvt_pair(v.z, v.w, h1, l1);
    int l   = i / (DIM*DIM/4);
    int rem = i % (DIM*DIM/4);
    int row = rem / (DIM/4);
    int c4  = rem % (DIM/4);
    size_t du2 = ((size_t)l*QKVD + which*DIM + row) * (DIM/4) + c4;
    ((uint2*)hi)[du2] = make_uint2(h0, h1);
    ((uint2*)lo)[du2] = make_uint2(l0, l1);
}

__global__ __launch_bounds__(256) void bias_qkv_kernel(
    const float* __restrict__ bq, const float* __restrict__ bk,
    const float* __restrict__ bv, float* __restrict__ bqkv)
{
    int i = blockIdx.x * blockDim.x + threadIdx.x;
    if (i >= NLAYER*QKVD) return;
    int l = i / QKVD, j = i % QKVD;
    float v;
    if (j < DIM)            v = bq[l*DIM + j];
    else if (j < 2*DIM)     v = bk[l*DIM + j - DIM];
    else                    v = bv[l*DIM + j - 2*DIM];
    bqkv[i] = v;
}

// ---------------- embedding (+ split) ----------------------------------------
__global__ __launch_bounds__(256) void embed_kernel(
    const int* __restrict__ input, const float* __restrict__ emb,
    float* __restrict__ h, uint32_t* __restrict__ hh, uint32_t* __restrict__ hl)
{
    int i  = blockIdx.x * blockDim.x + threadIdx.x;
    int n  = i / (DIM/4);
    int c4 = (i % (DIM/4)) * 4;
    int s  = n >> 1, b = n & 1;
    int tok = input[b*SEQ + s];
    float4 v = *(const float4*)&emb[(size_t)tok*DIM + c4];
    *(float4*)&h[(size_t)n*DIM + c4] = v;
    uint32_t h0, l0, h1, l1;
    cvt_pair(v.x, v.y, h0, l0);
    cvt_pair(v.z, v.w, h1, l1);
    size_t o = ((size_t)n*DIM + c4) >> 1;
    hh[o] = h0; hh[o+1] = h1;
    hl[o] = l0; hl[o+1] = l1;
}

// ---------- A_part[sp,b,h,dv,dq] = sum_{s in chunk} v[s,dv] * k[s,dq] ---------
__global__ __launch_bounds__(256) void attnA_kernel(
    const float* __restrict__ qkv, float* __restrict__ Apart)
{
    int bh = blockIdx.x;
    int sp = blockIdx.y;
    int b  = bh / HEADS, h = bh % HEADS;
    __shared__ float ks[16][64], vs[16][64];
    int tid = threadIdx.x;
    int dq  = tid & 63;
    int dvb = (tid >> 6) * 16;
    float acc[16];
    #pragma unroll
    for (int j = 0; j < 16; ++j) acc[j] = 0.f;

    int s0 = sp * SCHUNK;
    int r  = tid >> 4;
    int c  = (tid & 15) * 4;
    for (int st = 0; st < SCHUNK; st += 16) {
        int s = s0 + st + r;
        size_t base = ((size_t)(s*BATCH + b))*QKVD + h*DHEAD + c;
        *(float4*)&ks[r][c] = *(const float4*)&qkv[base + DIM];
        *(float4*)&vs[r][c] = *(const float4*)&qkv[base + 2*DIM];
        __syncthreads();
        #pragma unroll
        for (int ss = 0; ss < 16; ++ss) {
            float kq = ks[ss][dq];
            #pragma unroll
            for (int j = 0; j < 16; ++j)
                acc[j] = fmaf(vs[ss][dvb+j], kq, acc[j]);
        }
        __syncthreads();
    }
    float* out = Apart + ((size_t)sp*(BATCH*HEADS) + bh)*DHEAD*DHEAD;
    #pragma unroll
    for (int j = 0; j < 16; ++j) out[(dvb+j)*DHEAD + dq] = acc[j];
}

__global__ __launch_bounds__(256) void areduce_kernel(
    const float* __restrict__ Apart, float* __restrict__ Aout)
{
    int i = blockIdx.x * blockDim.x + threadIdx.x;
    float sum = 0.f;
    #pragma unroll 8
    for (int sp = 0; sp < NSPLIT; ++sp)
        sum += Apart[(size_t)sp*(BATCH*HEADS*DHEAD*DHEAD) + i];
    Aout[i] = sum;
}

// ---------- o = q . A  -> bf16 hi/lo split output -----------------------------
__global__ __launch_bounds__(256) void attnO_kernel(
    const float* __restrict__ qkv, const float* __restrict__ A,
    uint32_t* __restrict__ oh, uint32_t* __restrict__ ol)
{
    int h  = blockIdx.x, b = blockIdx.y;
    int s0 = blockIdx.z * 64;
    __shared__ float Asm[64][65];
    __shared__ float qs[64][64];
    int tid = threadIdx.x;
    const float* Ab = A + ((size_t)(b*HEADS + h))*DHEAD*DHEAD;
    for (int i = tid; i < 4096; i += 256) Asm[i >> 6][i & 63] = Ab[i];

    int r = tid >> 2;
    int c = (tid & 3) * 16;
    size_t qbase = ((size_t)((s0 + r)*BATCH + b))*QKVD + h*DHEAD + c;
    #pragma unroll
    for (int u = 0; u < 4; ++u)
        *(float4*)&qs[r][c + u*4] = *(const float4*)&qkv[qbase + u*4];
    __syncthreads();

    int dv2 = (tid & 31) * 2;
    int rb  = (tid >> 5) * 8;
    for (int rr = 0; rr < 8; ++rr) {
        float a0 = 0.f, a1 = 0.f;
        #pragma unroll
        for (int dq = 0; dq < 64; ++dq) {
            float qv = qs[rb+rr][dq];
            a0 = fmaf(qv, Asm[dv2][dq],   a0);
            a1 = fmaf(qv, Asm[dv2+1][dq], a1);
        }
        int s = s0 + rb + rr;
        uint32_t hh, ll;
        cvt_pair(a0, a1, hh, ll);
        size_t idx = (((size_t)(s*BATCH + b))*DIM + h*DHEAD + dv2) >> 1;
        oh[idx] = hh; ol[idx] = ll;
    }
}

// ---------------- layernorm: 2 rows/block, float4 per thread ------------------
__global__ __launch_bounds__(256) void ln_kernel(
    const float* __restrict__ x, const float* __restrict__ g,
    const float* __restrict__ be, float* __restrict__ out,
    uint32_t* __restrict__ oh, uint32_t* __restrict__ ol)
{
    __shared__ float s1[2][4], s2[2][4];
    const int row = threadIdx.x >> 7;       // 0..1
    const int t   = threadIdx.x & 127;      // 0..127, one float4 each
    const int n   = blockIdx.x * 2 + row;
    const float* xr = x + (size_t)n*DIM;
    float4 v = *(const float4*)(xr + t*4);
    float s  = (v.x + v.y) + (v.z + v.w);
    float sq = (v.x*v.x + v.y*v.y) + (v.z*v.z + v.w*v.w);
    #pragma unroll
    for (int o = 16; o; o >>= 1) {
        s  += __shfl_xor_sync(0xffffffffu, s , o);
        sq += __shfl_xor_sync(0xffffffffu, sq, o);
    }
    if ((t & 31) == 0) { s1[row][t >> 5] = s; s2[row][t >> 5] = sq; }
    __syncthreads();
    float ssum = (s1[row][0] + s1[row][1]) + (s1[row][2] + s1[row][3]);
    float qsum = (s2[row][0] + s2[row][1]) + (s2[row][2] + s2[row][3]);
    float mean = ssum * (1.0f/DIM);
    float var  = qsum * (1.0f/DIM) - mean*mean;
    float inv  = rsqrtf(var + 1e-5f);
    float4 gg = *(const float4*)(g  + t*4);
    float4 bb = *(const float4*)(be + t*4);
    float r0 = (v.x - mean)*inv*gg.x + bb.x;
    float r1 = (v.y - mean)*inv*gg.y + bb.y;
    float r2 = (v.z - mean)*inv*gg.z + bb.z;
    float r3 = (v.w - mean)*inv*gg.w + bb.w;
    *(float4*)(out + (size_t)n*DIM + t*4) = make_float4(r0, r1, r2, r3);
    uint32_t h0, l0, h1, l1;
    cvt_pair(r0, r1, h0, l0);
    cvt_pair(r2, r3, h1, l1);
    size_t idx = (size_t)n*(DIM/2) + t*2;
    oh[idx] = h0; oh[idx+1] = h1;
    ol[idx] = l0; ol[idx+1] = l1;
}

// ---------------- orchestration ----------------------------------------------
extern "C" void kernel_launch(void* const* d_in, const int* in_sizes, int n_in,
                              void* d_out, int out_size)
{
    (void)in_sizes; (void)n_in; (void)out_size;
    const int*   input = (const int*)  d_in[0];
    const float* emb   = (const float*)d_in[1];
    const float* Wq    = (const float*)d_in[2];
    const float* bq    = (const float*)d_in[3];
    const float* Wk    = (const float*)d_in[4];
    const float* bk    = (const float*)d_in[5];
    const float* Wv    = (const float*)d_in[6];
    const float* bv    = (const float*)d_in[7];
    const float* Wo    = (const float*)d_in[8];
    const float* bo    = (const float*)d_in[9];
    const float* W1    = (const float*)d_in[10];
    const float* b1    = (const float*)d_in[11];
    const float* W2    = (const float*)d_in[12];
    const float* b2    = (const float*)d_in[13];
    const float* g2    = (const float*)d_in[14];
    const float* be2   = (const float*)d_in[15];
    const float* Wfc   = (const float*)d_in[16];
    const float* bfc   = (const float*)d_in[17];

    float *h, *qkv, *tb, *Ab, *Apb, *bqkv;
    uint32_t *hh, *hl, *oh, *ol, *fh, *fl;
    uint32_t *wqkvh, *wqkvl, *woh, *wol, *w1h, *w1l, *w2h, *w2l, *wfh, *wfl;
    cudaGetSymbolAddress((void**)&h,    g_h);
    cudaGetSymbolAddress((void**)&qkv,  g_qkv);
    cudaGetSymbolAddress((void**)&tb,   g_t);
    cudaGetSymbolAddress((void**)&Ab,   g_A);
    cudaGetSymbolAddress((void**)&Apb,  g_Ap);
    cudaGetSymbolAddress((void**)&bqkv, g_bqkv);
    cudaGetSymbolAddress((void**)&hh,  g_hh);  cudaGetSymbolAddress((void**)&hl, g_hl);
    cudaGetSymbolAddress((void**)&oh,  g_oh);  cudaGetSymbolAddress((void**)&ol, g_ol);
    cudaGetSymbolAddress((void**)&fh,  g_fh);  cudaGetSymbolAddress((void**)&fl, g_fl);
    cudaGetSymbolAddress((void**)&wqkvh, g_wqkvh); cudaGetSymbolAddress((void**)&wqkvl, g_wqkvl);
    cudaGetSymbolAddress((void**)&woh, g_woh); cudaGetSymbolAddress((void**)&wol, g_wol);
    cudaGetSymbolAddress((void**)&w1h, g_w1h); cudaGetSymbolAddress((void**)&w1l, g_w1l);
    cudaGetSymbolAddress((void**)&w2h, g_w2h); cudaGetSymbolAddress((void**)&w2l, g_w2l);
    cudaGetSymbolAddress((void**)&wfh, g_wfh); cudaGetSymbolAddress((void**)&wfl, g_wfl);

    cudaFuncSetAttribute(tc_gemm<1>, cudaFuncAttributeMaxDynamicSharedMemorySize, SMEM_GEMM);
    cudaFuncSetAttribute(tc_gemm<2>, cudaFuncAttributeMaxDynamicSharedMemorySize, SMEM_GEMM);
    cudaFuncSetAttribute(tc_gemm<3>, cudaFuncAttributeMaxDynamicSharedMemorySize, SMEM_GEMM);
    cudaFuncSetAttribute(tc_gemm<4>, cudaFuncAttributeMaxDynamicSharedMemorySize, SMEM_GEMM);
    cudaFuncSetAttribute(tc_gemm<5>, cudaFuncAttributeMaxDynamicSharedMemorySize, SMEM_GEMM);

    // --- weight + bias prep (bulk, once per launch) ---
    {
        int nD = NLAYER*DIM*DIM/4, nF = NLAYER*FFD*DIM/4, nV = VOC*DIM/4;
        cvt_split_qkv_kernel<<<(nD+255)/256, 256>>>(Wq, wqkvh, wqkvl, 0);
        cvt_split_qkv_kernel<<<(nD+255)/256, 256>>>(Wk, wqkvh, wqkvl, 1);
        cvt_split_qkv_kernel<<<(nD+255)/256, 256>>>(Wv, wqkvh, wqkvl, 2);
        cvt_split_kernel<<<(nD+255)/256, 256>>>(Wo, woh, wol, nD);
        cvt_split_kernel<<<(nF+255)/256, 256>>>(W1, w1h, w1l, nF);
        cvt_split_kernel<<<(nF+255)/256, 256>>>(W2, w2h, w2l, nF);
        cvt_split_kernel<<<(nV+255)/256, 256>>>(Wfc, wfh, wfl, nV);
        bias_qkv_kernel<<<(NLAYER*QKVD+255)/256, 256>>>(bq, bk, bv, bqkv);
    }

    embed_kernel<<<(NTOK*DIM/4)/256, 256>>>(input, emb, h, hh, hl);

    const dim3 gQKV(QKVD/TCN, NTOK/TCM);   // (12, 64)
    const dim3 gD  (DIM/TCN,  NTOK/TCM);   // (4, 64)
    const dim3 gFF (FFD/TCN,  NTOK/TCM);   // (16, 64)
    const dim3 gV  (VOC/TCN,  NTOK/TCM);   // (32, 64)

    for (int l = 0; l < NLAYER; ++l) {
        const size_t oQ = (size_t)l*QKVD*DIM/2;
        const size_t oD = (size_t)l*DIM*DIM/2;
        const size_t oF = (size_t)l*FFD*DIM/2;
        const float* bol = bo + l*DIM;
        const float* b1l = b1 + l*FFD;
        const float* b2l = b2 + l*DIM;
        const float* g2l = g2 + l*DIM;
        const float* be2l= be2+ l*DIM;

        // QKV = h @ [Wq;Wk;Wv]^T + bias, fused unit/unitelu per segment
        tc_gemm<5><<<gQKV, 256, SMEM_GEMM>>>(hh, hl, wqkvh+oQ, wqkvl+oQ,
                                             bqkv + l*QKVD, nullptr,
                                             qkv, nullptr, nullptr, NTOK, QKVD, DIM);
        attnA_kernel<<<dim3(BATCH*HEADS, NSPLIT), 256>>>(qkv, Apb);
        areduce_kernel<<<(BATCH*HEADS*DHEAD*DHEAD)/256, 256>>>(Apb, Ab);
        attnO_kernel<<<dim3(HEADS, BATCH, SEQ/64), 256>>>(qkv, Ab, oh, ol);
        // h = h + o Wo^T + bo  (fp32 residual, writes fp32 h + splits)
        tc_gemm<3><<<gD, 256, SMEM_GEMM>>>(oh, ol, woh+oD, wol+oD, bol, h,
                                           h, hh, hl, NTOK, DIM, DIM);
        // f = relu(h W1^T + b1)  (splits)
        tc_gemm<1><<<gFF, 256, SMEM_GEMM>>>(hh, hl, w1h+oF, w1l+oF, b1l, nullptr,
                                            nullptr, fh, fl, NTOK, FFD, DIM);
        // t = h + f W2^T + b2  (fp32 residual, fp32 out for LN)
        tc_gemm<2><<<gD, 256, SMEM_GEMM>>>(fh, fl, w2h+oF, w2l+oF, b2l, h,
                                           tb, nullptr, nullptr, NTOK, DIM, FFD);
        // h = LN(t)  (fp32 h + splits), 2 rows per block
        ln_kernel<<<NTOK/2, 256>>>(tb, g2l, be2l, h, hh, hl);
    }

    // logits, written directly transposed into d_out [B, V, S]
    tc_gemm<4><<<gV, 256, SMEM_GEMM>>>(hh, hl, wfh, wfl, bfc, nullptr,
                                       (float*)d_out, nullptr, nullptr, NTOK, VOC, DIM);
}

// round 17
// speedup vs baseline: 1.0086x; 1.0042x over previous
#include <cuda_runtime.h>
#include <cstdint>
#include <cstddef>

// ---------------- problem constants ----------------
#define BATCH   2
#define SEQ     4096
#define NTOK    (BATCH*SEQ)     // 8192, n = s*BATCH + b
#define DIM     512
#define HEADS   8
#define DHEAD   64
#define FFD     2048
#define VOC     4096
#define NLAYER  6
#define NSPLIT  64
#define SCHUNK  (SEQ / NSPLIT)  // 64
#define QKVD    (3*DIM)         // 1536

// ---------------- scratch (static device allocation only) ----------------
__device__ float g_h   [NTOK*DIM];
__device__ float g_qkv [NTOK*QKVD];
__device__ float g_t   [NTOK*DIM];
__device__ float g_A   [BATCH*HEADS*DHEAD*DHEAD];
__device__ float g_Ap  [NSPLIT*BATCH*HEADS*DHEAD*DHEAD];
__device__ float g_bqkv[NLAYER*QKVD];

// bf16 hi/lo split buffers (packed 2 bf16 per u32)
__device__ uint32_t g_hh[NTOK*DIM/2],  g_hl[NTOK*DIM/2];
__device__ uint32_t g_oh[NTOK*DIM/2],  g_ol[NTOK*DIM/2];
__device__ uint32_t g_fh[NTOK*FFD/2],  g_fl[NTOK*FFD/2];
__device__ uint32_t g_wqkvh[NLAYER*QKVD*DIM/2], g_wqkvl[NLAYER*QKVD*DIM/2];
__device__ uint32_t g_woh[NLAYER*DIM*DIM/2],  g_wol[NLAYER*DIM*DIM/2];
__device__ uint32_t g_w1h[NLAYER*FFD*DIM/2],  g_w1l[NLAYER*FFD*DIM/2];
__device__ uint32_t g_w2h[NLAYER*FFD*DIM/2],  g_w2l[NLAYER*FFD*DIM/2];
__device__ uint32_t g_wfh[VOC*DIM/2],         g_wfl[VOC*DIM/2];

// ================= helpers ==================================================
__device__ __forceinline__ uint32_t smem_u32(const void* p) {
    uint32_t a;
    asm("{ .reg .u64 t; cvta.to.shared.u64 t, %1; cvt.u32.u64 %0, t; }"
        : "=r"(a) : "l"(p));
    return a;
}
__device__ __forceinline__ uint32_t bf16rn(float x) {
    uint32_t u = __float_as_uint(x);
    return (u + 0x7fffu + ((u >> 16) & 1u)) >> 16;
}
__device__ __forceinline__ void cvt_pair(float a, float b, uint32_t& hi, uint32_t& lo) {
    uint32_t ah = bf16rn(a), bh = bf16rn(b);
    float ar = a - __uint_as_float(ah << 16);
    float br = b - __uint_as_float(bh << 16);
    hi = ah | (bh << 16);
    lo = bf16rn(ar) | (bf16rn(br) << 16);
}
__device__ __forceinline__ void ldm4(uint32_t& r0, uint32_t& r1, uint32_t& r2,
                                     uint32_t& r3, uint32_t a) {
    asm volatile("ldmatrix.sync.aligned.m8n8.x4.shared.b16 {%0,%1,%2,%3}, [%4];"
                 : "=r"(r0), "=r"(r1), "=r"(r2), "=r"(r3) : "r"(a));
}
__device__ __forceinline__ void mma16816(float* c,
    uint32_t a0, uint32_t a1, uint32_t a2, uint32_t a3, uint32_t b0, uint32_t b1) {
    asm volatile(
        "mma.sync.aligned.m16n8k16.row.col.f32.bf16.bf16.f32 "
        "{%0,%1,%2,%3}, {%4,%5,%6,%7}, {%8,%9}, {%0,%1,%2,%3};"
        : "+f"(c[0]), "+f"(c[1]), "+f"(c[2]), "+f"(c[3])
        : "r"(a0), "r"(a1), "r"(a2), "r"(a3), "r"(b0), "r"(b1));
}
__device__ __forceinline__ void cp_async16(uint32_t dst, const void* src) {
    asm volatile("cp.async.cg.shared.global [%0], [%1], 16;"
                 :: "r"(dst), "l"(src));
}
__device__ __forceinline__ void cp_commit() {
    asm volatile("cp.async.commit_group;" ::: "memory");
}
template<int N>
__device__ __forceinline__ void cp_wait() {
    asm volatile("cp.async.wait_group %0;" :: "n"(N) : "memory");
}

// ================= tensor-core GEMM (bf16 hi/lo, cp.async 3-stage) ==========
// C[M,Nc] = (Ah+Al)[M,K] @ (Wh+Wl)[Nc,K]^T + bias via Ah*Wh + Ah*Wl + Al*Wh.
// MODE: 1 bias+relu->splits | 2 bias+res(fp32)->fp32 | 3 bias+res(fp32)->fp32+splits
//       4 bias->fp32 transposed [B,V,S] (smem-staged coalesced store)
//       5 bias+per-head norm(seg)->fp32
#define TCM 128
#define TCN 128
#define TCK 32
#define TILE_B 8192               // 128 rows * 64B (swizzled, no pad)
#define OFF_AHI 0
#define OFF_ALO (1*TILE_B)
#define OFF_BHI (2*TILE_B)
#define OFF_BLO (3*TILE_B)
#define STAGE_B (4*TILE_B)        // 32768
#define NSTAGE  3
#define SMEM_GEMM (NSTAGE*STAGE_B) // 98304

__device__ __forceinline__ uint32_t sw_off(uint32_t row, uint32_t c16) {
    return row * 64u + ((c16 ^ (row & 3u) ^ ((row >> 2) & 1u)) * 16u);
}

template<int MODE>
__global__ __launch_bounds__(256, 2) void tc_gemm(
    const uint32_t* __restrict__ Ah, const uint32_t* __restrict__ Al,
    const uint32_t* __restrict__ Wh, const uint32_t* __restrict__ Wl,
    const float* __restrict__ bias, const float* __restrict__ res,
    float* __restrict__ C, uint32_t* __restrict__ Ch, uint32_t* __restrict__ Cl,
    int M, int Nc, int K)
{
    extern __shared__ char smem[];
    const uint32_t sb = smem_u32(smem);
    const int tid  = threadIdx.x, wid = tid >> 5, lane = tid & 31;
    const int bn   = blockIdx.x * TCN, bm = blockIdx.y * TCM;
    const int m0   = (wid & 3) * 32;
    const int n0   = (wid >> 2) * 64;
    const int CCH  = K / TCK;

    const char* pAh = (const char*)Ah;
    const char* pAl = (const char*)Al;
    const char* pWh = (const char*)Wh;
    const char* pWl = (const char*)Wl;

    auto issue_chunk = [&](int c) {
        const uint32_t st = sb + (uint32_t)(c % NSTAGE) * STAGE_B;
        #pragma unroll
        for (int t = 0; t < 2; ++t) {
            const int e   = tid + t * 256;
            const uint32_t row = (uint32_t)(e >> 2);
            const uint32_t c16 = (uint32_t)(e & 3);
            const uint32_t d   = st + sw_off(row, c16);
            const size_t ga = ((size_t)(bm + row) * K + c * TCK) * 2 + c16 * 16u;
            const size_t gb = ((size_t)(bn + row) * K + c * TCK) * 2 + c16 * 16u;
            cp_async16(d + OFF_AHI, pAh + ga);
            cp_async16(d + OFF_ALO, pAl + ga);
            cp_async16(d + OFF_BHI, pWh + gb);
            cp_async16(d + OFF_BLO, pWl + gb);
        }
        cp_commit();
    };

    float acc[2][8][4];
    #pragma unroll
    for (int mi = 0; mi < 2; ++mi)
        #pragma unroll
        for (int ni = 0; ni < 8; ++ni)
            #pragma unroll
            for (int j = 0; j < 4; ++j) acc[mi][ni][j] = 0.f;

    const uint32_t rl   = (uint32_t)(lane & 15);
    const uint32_t cb   = (uint32_t)(lane >> 4);
    const uint32_t x    = (rl & 3u) ^ ((rl >> 2) & 1u);
    const uint32_t rbyt = rl * 64u;
    const uint32_t s0   = ((cb ^ x) * 16u);

    issue_chunk(0);
    issue_chunk(1);

    for (int c = 0; c < CCH; ++c) {
        cp_wait<1>();
        __syncthreads();
        const uint32_t st = sb + (uint32_t)(c % NSTAGE) * STAGE_B;
        const uint32_t aof = st + rbyt + (uint32_t)m0 * 64u;
        const uint32_t bof = st + rbyt + (uint32_t)n0 * 64u;
        #pragma unroll
        for (int kk = 0; kk < 2; ++kk) {
            const uint32_t sl = s0 ^ (kk ? 32u : 0u);
            uint32_t ah[2][4], al[2][4], bh[4][4], bl[4][4];
            ldm4(ah[0][0], ah[0][1], ah[0][2], ah[0][3], aof + OFF_AHI + sl);
            ldm4(ah[1][0], ah[1][1], ah[1][2], ah[1][3], aof + OFF_AHI + 1024u + sl);
            #pragma unroll
            for (int nj = 0; nj < 4; ++nj)
                ldm4(bh[nj][0], bh[nj][1], bh[nj][2], bh[nj][3],
                     bof + OFF_BHI + (uint32_t)nj * 1024u + sl);
            #pragma unroll
            for (int mi = 0; mi < 2; ++mi)
                #pragma unroll
                for (int nj = 0; nj < 4; ++nj) {
                    mma16816(acc[mi][2*nj],   ah[mi][0], ah[mi][1], ah[mi][2], ah[mi][3],
                             bh[nj][0], bh[nj][2]);
                    mma16816(acc[mi][2*nj+1], ah[mi][0], ah[mi][1], ah[mi][2], ah[mi][3],
                             bh[nj][1], bh[nj][3]);
                }
            #pragma unroll
            for (int nj = 0; nj < 4; ++nj)
                ldm4(bl[nj][0], bl[nj][1], bl[nj][2], bl[nj][3],
                     bof + OFF_BLO + (uint32_t)nj * 1024u + sl);
            #pragma unroll
            for (int mi = 0; mi < 2; ++mi)
                #pragma unroll
                for (int nj = 0; nj < 4; ++nj) {
                    mma16816(acc[mi][2*nj],   ah[mi][0], ah[mi][1], ah[mi][2], ah[mi][3],
                             bl[nj][0], bl[nj][2]);
                    mma16816(acc[mi][2*nj+1], ah[mi][0], ah[mi][1], ah[mi][2], ah[mi][3],
                             bl[nj][1], bl[nj][3]);
                }
            ldm4(al[0][0], al[0][1], al[0][2], al[0][3], aof + OFF_ALO + sl);
            ldm4(al[1][0], al[1][1], al[1][2], al[1][3], aof + OFF_ALO + 1024u + sl);
            #pragma unroll
            for (int mi = 0; mi < 2; ++mi)
                #pragma unroll
                for (int nj = 0; nj < 4; ++nj) {
                    mma16816(acc[mi][2*nj],   al[mi][0], al[mi][1], al[mi][2], al[mi][3],
                             bh[nj][0], bh[nj][2]);
                    mma16816(acc[mi][2*nj+1], al[mi][0], al[mi][1], al[mi][2], al[mi][3],
                             bh[nj][1], bh[nj][3]);
                }
        }
        if (c + NSTAGE - 1 < CCH) issue_chunk(c + NSTAGE - 1);
    }

    // ---------------- epilogue ----------------
    const int g = lane >> 2, qq = lane & 3;

    if (MODE == 4) {
        // stage 128x128 fp32 tile in smem (pitch 129 -> conflict-free column
        // reads), then write fully coalesced 256B column runs to out[b][v][s].
        float* stag = (float*)smem;
        __syncthreads();   // all warps done reading stage buffers
        #pragma unroll
        for (int mi = 0; mi < 2; ++mi) {
            const int rloc0 = m0 + mi * 16 + g;
            #pragma unroll
            for (int ni = 0; ni < 8; ++ni) {
                const int cl = n0 + ni * 8 + 2 * qq;
                float2 bb = *(const float2*)&bias[bn + cl];
                stag[rloc0 * 129 + cl]           = acc[mi][ni][0] + bb.x;
                stag[rloc0 * 129 + cl + 1]       = acc[mi][ni][1] + bb.y;
                stag[(rloc0 + 8) * 129 + cl]     = acc[mi][ni][2] + bb.x;
                stag[(rloc0 + 8) * 129 + cl + 1] = acc[mi][ni][3] + bb.y;
            }
        }
        __syncthreads();
        const int sbase = bm >> 1;   // bm even; 64 s-values per b in this tile
        for (int i = tid; i < 128 * 128; i += 256) {
            const int col  = i >> 7;
            const int rem  = i & 127;
            const int b    = rem >> 6;
            const int sidx = rem & 63;
            const int row  = 2 * sidx + b;
            C[((size_t)b * Nc + bn + col) * SEQ + sbase + sidx] =
                stag[row * 129 + col];
        }
        return;
    }

    #pragma unroll
    for (int mi = 0; mi < 2; ++mi) {
        const int r0 = bm + m0 + mi * 16 + g;
        float v[8][4];
        float ss0 = 0.f, ss1 = 0.f;
        #pragma unroll
        for (int ni = 0; ni < 8; ++ni) {
            const int col = bn + n0 + ni * 8 + 2 * qq;
            float2 bb = *(const float2*)&bias[col];
            v[ni][0] = acc[mi][ni][0] + bb.x;
            v[ni][1] = acc[mi][ni][1] + bb.y;
            v[ni][2] = acc[mi][ni][2] + bb.x;
            v[ni][3] = acc[mi][ni][3] + bb.y;
            if (MODE == 5) {
                ss0 += v[ni][0]*v[ni][0] + v[ni][1]*v[ni][1];
                ss1 += v[ni][2]*v[ni][2] + v[ni][3]*v[ni][3];
            }
        }
        if (MODE == 5) {
            const int seg = (bn + n0) >> 9;     // 0=Q(unit) 1=K(unitelu) 2=V(none)
            if (seg < 2) {
                ss0 += __shfl_xor_sync(0xffffffffu, ss0, 1);
                ss0 += __shfl_xor_sync(0xffffffffu, ss0, 2);
                ss1 += __shfl_xor_sync(0xffffffffu, ss1, 1);
                ss1 += __shfl_xor_sync(0xffffffffu, ss1, 2);
                float inv0 = rsqrtf(ss0), inv1 = rsqrtf(ss1);
                #pragma unroll
                for (int ni = 0; ni < 8; ++ni) {
                    v[ni][0] *= inv0; v[ni][1] *= inv0;
                    v[ni][2] *= inv1; v[ni][3] *= inv1;
                    if (seg == 1) {
                        #pragma unroll
                        for (int j = 0; j < 4; ++j)
                            v[ni][j] = v[ni][j] > 0.f ? v[ni][j] : expm1f(v[ni][j]);
                    }
                }
            }
        }
        #pragma unroll
        for (int ni = 0; ni < 8; ++ni) {
            const int col = bn + n0 + ni * 8 + 2 * qq;
            float v0 = v[ni][0], v1 = v[ni][1], v2 = v[ni][2], v3 = v[ni][3];
            if (MODE == 1) {
                v0 = fmaxf(v0, 0.f); v1 = fmaxf(v1, 0.f);
                v2 = fmaxf(v2, 0.f); v3 = fmaxf(v3, 0.f);
            }
            if (MODE == 2 || MODE == 3) {
                float2 r0v = *(const float2*)&res[(size_t)r0 * Nc + col];
                float2 r1v = *(const float2*)&res[(size_t)(r0 + 8) * Nc + col];
                v0 += r0v.x; v1 += r0v.y; v2 += r1v.x; v3 += r1v.y;
            }
            if (MODE == 2 || MODE == 3 || MODE == 5) {
                *(float2*)&C[(size_t)r0 * Nc + col]       = make_float2(v0, v1);
                *(float2*)&C[(size_t)(r0 + 8) * Nc + col] = make_float2(v2, v3);
            }
            if (MODE == 1 || MODE == 3) {
                uint32_t h0, l0, h1, l1;
                cvt_pair(v0, v1, h0, l0);
                cvt_pair(v2, v3, h1, l1);
                size_t i0 = ((size_t)r0 * Nc + col) >> 1;
                size_t i1 = ((size_t)(r0 + 8) * Nc + col) >> 1;
                Ch[i0] = h0; Cl[i0] = l0;
                Ch[i1] = h1; Cl[i1] = l1;
            }
        }
    }
}

// ---------------- fp32 -> bf16 hi/lo split (bulk convert) --------------------
__global__ __launch_bounds__(256) void cvt_split_kernel(
    const float* __restrict__ x, uint32_t* __restrict__ hi,
    uint32_t* __restrict__ lo, int n4)
{
    int i = blockIdx.x * blockDim.x + threadIdx.x;
    if (i >= n4) return;
    float4 v = ((const float4*)x)[i];
    uint32_t h0, l0, h1, l1;
    cvt_pair(v.x, v.y, h0, l0);
    cvt_pair(v.z, v.w, h1, l1);
    ((uint2*)hi)[i] = make_uint2(h0, h1);
    ((uint2*)lo)[i] = make_uint2(l0, l1);
}

// split Wq/Wk/Wv [L][512][512] into wqkv [L][1536][512] slot `which`
__global__ __launch_bounds__(256) void cvt_split_qkv_kernel(
    const float* __restrict__ x, uint32_t* __restrict__ hi,
    uint32_t* __restrict__ lo, int which)
{
    int i = blockIdx.x * blockDim.x + threadIdx.x;
    if (i >= NLAYER*DIM*DIM/4) return;
    float4 v = ((const float4*)x)[i];
    uint32_t h0, l0, h1, l1;
    cvt_pair(v.x, v.y, h0, l0);
    cvt_pair(v.z, v.w, h1, l1);
    int l   = i / (DIM*DIM/4);
    int rem = i % (DIM*DIM/4);
    int row = rem / (DIM/4);
    int c4  = rem % (DIM/4);
    size_t du2 = ((size_t)l*QKVD + which*DIM + row) * (DIM/4) + c4;
    ((uint2*)hi)[du2] = make_uint2(h0, h1);
    ((uint2*)lo)[du2] = make_uint2(l0, l1);
}

__global__ __launch_bounds__(256) void bias_qkv_kernel(
    const float* __restrict__ bq, const float* __restrict__ bk,
    const float* __restrict__ bv, float* __restrict__ bqkv)
{
    int i = blockIdx.x * blockDim.x + threadIdx.x;
    if (i >= NLAYER*QKVD) return;
    int l = i / QKVD, j = i % QKVD;
    float v;
    if (j < DIM)            v = bq[l*DIM + j];
    else if (j < 2*DIM)     v = bk[l*DIM + j - DIM];
    else                    v = bv[l*DIM + j - 2*DIM];
    bqkv[i] = v;
}

// ---------------- embedding (+ split) ----------------------------------------
__global__ __launch_bounds__(256) void embed_kernel(
    const int* __restrict__ input, const float* __restrict__ emb,
    float* __restrict__ h, uint32_t* __restrict__ hh, uint32_t* __restrict__ hl)
{
    int i  = blockIdx.x * blockDim.x + threadIdx.x;
    int n  = i / (DIM/4);
    int c4 = (i % (DIM/4)) * 4;
    int s  = n >> 1, b = n & 1;
    int tok = input[b*SEQ + s];
    float4 v = *(const float4*)&emb[(size_t)tok*DIM + c4];
    *(float4*)&h[(size_t)n*DIM + c4] = v;
    uint32_t h0, l0, h1, l1;
    cvt_pair(v.x, v.y, h0, l0);
    cvt_pair(v.z, v.w, h1, l1);
    size_t o = ((size_t)n*DIM + c4) >> 1;
    hh[o] = h0; hh[o+1] = h1;
    hl[o] = l0; hl[o+1] = l1;
}

// ---------- A_part[sp,b,h,dv,dq] = sum_{s in chunk} v[s,dv] * k[s,dq] ---------
__global__ __launch_bounds__(256) void attnA_kernel(
    const float* __restrict__ qkv, float* __restrict__ Apart)
{
    int bh = blockIdx.x;
    int sp = blockIdx.y;
    int b  = bh / HEADS, h = bh % HEADS;
    __shared__ float ks[16][64], vs[16][64];
    int tid = threadIdx.x;
    int dq  = tid & 63;
    int dvb = (tid >> 6) * 16;
    float acc[16];
    #pragma unroll
    for (int j = 0; j < 16; ++j) acc[j] = 0.f;

    int s0 = sp * SCHUNK;
    int r  = tid >> 4;
    int c  = (tid & 15) * 4;
    for (int st = 0; st < SCHUNK; st += 16) {
        int s = s0 + st + r;
        size_t base = ((size_t)(s*BATCH + b))*QKVD + h*DHEAD + c;
        *(float4*)&ks[r][c] = *(const float4*)&qkv[base + DIM];
        *(float4*)&vs[r][c] = *(const float4*)&qkv[base + 2*DIM];
        __syncthreads();
        #pragma unroll
        for (int ss = 0; ss < 16; ++ss) {
            float kq = ks[ss][dq];
            #pragma unroll
            for (int j = 0; j < 16; ++j)
                acc[j] = fmaf(vs[ss][dvb+j], kq, acc[j]);
        }
        __syncthreads();
    }
    float* out = Apart + ((size_t)sp*(BATCH*HEADS) + bh)*DHEAD*DHEAD;
    #pragma unroll
    for (int j = 0; j < 16; ++j) out[(dvb+j)*DHEAD + dq] = acc[j];
}

// vectorized: each thread sums one float4 column over NSPLIT partials
__global__ __launch_bounds__(256) void areduce_kernel(
    const float* __restrict__ Apart, float* __restrict__ Aout)
{
    int i = blockIdx.x * blockDim.x + threadIdx.x;   // over BATCH*HEADS*4096/4
    float4 sum = make_float4(0.f, 0.f, 0.f, 0.f);
    #pragma unroll 8
    for (int sp = 0; sp < NSPLIT; ++sp) {
        float4 v = ((const float4*)Apart)[(size_t)sp*(BATCH*HEADS*DHEAD*DHEAD/4) + i];
        sum.x += v.x; sum.y += v.y; sum.z += v.z; sum.w += v.w;
    }
    ((float4*)Aout)[i] = sum;
}

// ---------- o = q . A  -> splits; 128 seq rows per block (A loaded once) ------
__global__ __launch_bounds__(256) void attnO_kernel(
    const float* __restrict__ qkv, const float* __restrict__ A,
    uint32_t* __restrict__ oh, uint32_t* __restrict__ ol)
{
    int h  = blockIdx.x, b = blockIdx.y;
    int sB = blockIdx.z * 128;
    __shared__ float Asm[64][65];
    __shared__ float qs[64][64];
    int tid = threadIdx.x;
    const float* Ab = A + ((size_t)(b*HEADS + h))*DHEAD*DHEAD;
    for (int i = tid; i < 4096; i += 256) Asm[i >> 6][i & 63] = Ab[i];

    int r = tid >> 2;
    int c = (tid & 3) * 16;
    int dv2 = (tid & 31) * 2;
    int rb  = (tid >> 5) * 8;

    #pragma unroll
    for (int half = 0; half < 2; ++half) {
        const int s0 = sB + half * 64;
        size_t qbase = ((size_t)((s0 + r)*BATCH + b))*QKVD + h*DHEAD + c;
        __syncthreads();             // qs free (and Asm ready on first pass)
        #pragma unroll
        for (int u = 0; u < 4; ++u)
            *(float4*)&qs[r][c + u*4] = *(const float4*)&qkv[qbase + u*4];
        __syncthreads();

        for (int rr = 0; rr < 8; ++rr) {
            float a0 = 0.f, a1 = 0.f;
            #pragma unroll
            for (int dq = 0; dq < 64; ++dq) {
                float qv = qs[rb+rr][dq];
                a0 = fmaf(qv, Asm[dv2][dq],   a0);
                a1 = fmaf(qv, Asm[dv2+1][dq], a1);
            }
            int s = s0 + rb + rr;
            uint32_t hh, ll;
            cvt_pair(a0, a1, hh, ll);
            size_t idx = (((size_t)(s*BATCH + b))*DIM + h*DHEAD + dv2) >> 1;
            oh[idx] = hh; ol[idx] = ll;
        }
    }
}

// ---------------- layernorm: 2 rows/block, float4 per thread ------------------
__global__ __launch_bounds__(256) void ln_kernel(
    const float* __restrict__ x, const float* __restrict__ g,
    const float* __restrict__ be, float* __restrict__ out,
    uint32_t* __restrict__ oh, uint32_t* __restrict__ ol)
{
    __shared__ float s1[2][4], s2[2][4];
    const int row = threadIdx.x >> 7;       // 0..1
    const int t   = threadIdx.x & 127;      // 0..127, one float4 each
    const int n   = blockIdx.x * 2 + row;
    const float* xr = x + (size_t)n*DIM;
    float4 v = *(const float4*)(xr + t*4);
    float s  = (v.x + v.y) + (v.z + v.w);
    float sq = (v.x*v.x + v.y*v.y) + (v.z*v.z + v.w*v.w);
    #pragma unroll
    for (int o = 16; o; o >>= 1) {
        s  += __shfl_xor_sync(0xffffffffu, s , o);
        sq += __shfl_xor_sync(0xffffffffu, sq, o);
    }
    if ((t & 31) == 0) { s1[row][t >> 5] = s; s2[row][t >> 5] = sq; }
    __syncthreads();
    float ssum = (s1[row][0] + s1[row][1]) + (s1[row][2] + s1[row][3]);
    float qsum = (s2[row][0] + s2[row][1]) + (s2[row][2] + s2[row][3]);
    float mean = ssum * (1.0f/DIM);
    float var  = qsum * (1.0f/DIM) - mean*mean;
    float inv  = rsqrtf(var + 1e-5f);
    float4 gg = *(const float4*)(g  + t*4);
    float4 bb = *(const float4*)(be + t*4);
    float r0 = (v.x - mean)*inv*gg.x + bb.x;
    float r1 = (v.y - mean)*inv*gg.y + bb.y;
    float r2 = (v.z - mean)*inv*gg.z + bb.z;
    float r3 = (v.w - mean)*inv*gg.w + bb.w;
    *(float4*)(out + (size_t)n*DIM + t*4) = make_float4(r0, r1, r2, r3);
    uint32_t h0, l0, h1, l1;
    cvt_pair(r0, r1, h0, l0);
    cvt_pair(r2, r3, h1, l1);
    size_t idx = (size_t)n*(DIM/2) + t*2;
    oh[idx] = h0; oh[idx+1] = h1;
    ol[idx] = l0; ol[idx+1] = l1;
}

// ---------------- orchestration ----------------------------------------------
extern "C" void kernel_launch(void* const* d_in, const int* in_sizes, int n_in,
                              void* d_out, int out_size)
{
    (void)in_sizes; (void)n_in; (void)out_size;
    const int*   input = (const int*)  d_in[0];
    const float* emb   = (const float*)d_in[1];
    const float* Wq    = (const float*)d_in[2];
    const float* bq    = (const float*)d_in[3];
    const float* Wk    = (const float*)d_in[4];
    const float* bk    = (const float*)d_in[5];
    const float* Wv    = (const float*)d_in[6];
    const float* bv    = (const float*)d_in[7];
    const float* Wo    = (const float*)d_in[8];
    const float* bo    = (const float*)d_in[9];
    const float* W1    = (const float*)d_in[10];
    const float* b1    = (const float*)d_in[11];
    const float* W2    = (const float*)d_in[12];
    const float* b2    = (const float*)d_in[13];
    const float* g2    = (const float*)d_in[14];
    const float* be2   = (const float*)d_in[15];
    const float* Wfc   = (const float*)d_in[16];
    const float* bfc   = (const float*)d_in[17];

    float *h, *qkv, *tb, *Ab, *Apb, *bqkv;
    uint32_t *hh, *hl, *oh, *ol, *fh, *fl;
    uint32_t *wqkvh, *wqkvl, *woh, *wol, *w1h, *w1l, *w2h, *w2l, *wfh, *wfl;
    cudaGetSymbolAddress((void**)&h,    g_h);
    cudaGetSymbolAddress((void**)&qkv,  g_qkv);
    cudaGetSymbolAddress((void**)&tb,   g_t);
    cudaGetSymbolAddress((void**)&Ab,   g_A);
    cudaGetSymbolAddress((void**)&Apb,  g_Ap);
    cudaGetSymbolAddress((void**)&bqkv, g_bqkv);
    cudaGetSymbolAddress((void**)&hh,  g_hh);  cudaGetSymbolAddress((void**)&hl, g_hl);
    cudaGetSymbolAddress((void**)&oh,  g_oh);  cudaGetSymbolAddress((void**)&ol, g_ol);
    cudaGetSymbolAddress((void**)&fh,  g_fh);  cudaGetSymbolAddress((void**)&fl, g_fl);
    cudaGetSymbolAddress((void**)&wqkvh, g_wqkvh); cudaGetSymbolAddress((void**)&wqkvl, g_wqkvl);
    cudaGetSymbolAddress((void**)&woh, g_woh); cudaGetSymbolAddress((void**)&wol, g_wol);
    cudaGetSymbolAddress((void**)&w1h, g_w1h); cudaGetSymbolAddress((void**)&w1l, g_w1l);
    cudaGetSymbolAddress((void**)&w2h, g_w2h); cudaGetSymbolAddress((void**)&w2l, g_w2l);
    cudaGetSymbolAddress((void**)&wfh, g_wfh); cudaGetSymbolAddress((void**)&wfl, g_wfl);

    cudaFuncSetAttribute(tc_gemm<1>, cudaFuncAttributeMaxDynamicSharedMemorySize, SMEM_GEMM);
    cudaFuncSetAttribute(tc_gemm<2>, cudaFuncAttributeMaxDynamicSharedMemorySize, SMEM_GEMM);
    cudaFuncSetAttribute(tc_gemm<3>, cudaFuncAttributeMaxDynamicSharedMemorySize, SMEM_GEMM);
    cudaFuncSetAttribute(tc_gemm<4>, cudaFuncAttributeMaxDynamicSharedMemorySize, SMEM_GEMM);
    cudaFuncSetAttribute(tc_gemm<5>, cudaFuncAttributeMaxDynamicSharedMemorySize, SMEM_GEMM);

    // --- weight + bias prep (bulk, once per launch) ---
    {
        int nD = NLAYER*DIM*DIM/4, nF = NLAYER*FFD*DIM/4, nV = VOC*DIM/4;
        cvt_split_qkv_kernel<<<(nD+255)/256, 256>>>(Wq, wqkvh, wqkvl, 0);
        cvt_split_qkv_kernel<<<(nD+255)/256, 256>>>(Wk, wqkvh, wqkvl, 1);
        cvt_split_qkv_kernel<<<(nD+255)/256, 256>>>(Wv, wqkvh, wqkvl, 2);
        cvt_split_kernel<<<(nD+255)/256, 256>>>(Wo, woh, wol, nD);
        cvt_split_kernel<<<(nF+255)/256, 256>>>(W1, w1h, w1l, nF);
        cvt_split_kernel<<<(nF+255)/256, 256>>>(W2, w2h, w2l, nF);
        cvt_split_kernel<<<(nV+255)/256, 256>>>(Wfc, wfh, wfl, nV);
        bias_qkv_kernel<<<(NLAYER*QKVD+255)/256, 256>>>(bq, bk, bv, bqkv);
    }

    embed_kernel<<<(NTOK*DIM/4)/256, 256>>>(input, emb, h, hh, hl);

    const dim3 gQKV(QKVD/TCN, NTOK/TCM);   // (12, 64)
    const dim3 gD  (DIM/TCN,  NTOK/TCM);   // (4, 64)
    const dim3 gFF (FFD/TCN,  NTOK/TCM);   // (16, 64)
    const dim3 gV  (VOC/TCN,  NTOK/TCM);   // (32, 64)

    for (int l = 0; l < NLAYER; ++l) {
        const size_t oQ = (size_t)l*QKVD*DIM/2;
        const size_t oD = (size_t)l*DIM*DIM/2;
        const size_t oF = (size_t)l*FFD*DIM/2;
        const float* bol = bo + l*DIM;
        const float* b1l = b1 + l*FFD;
        const float* b2l = b2 + l*DIM;
        const float* g2l = g2 + l*DIM;
        const float* be2l= be2+ l*DIM;

        // QKV = h @ [Wq;Wk;Wv]^T + bias, fused unit/unitelu per segment
        tc_gemm<5><<<gQKV, 256, SMEM_GEMM>>>(hh, hl, wqkvh+oQ, wqkvl+oQ,
                                             bqkv + l*QKVD, nullptr,
                                             qkv, nullptr, nullptr, NTOK, QKVD, DIM);
        attnA_kernel<<<dim3(BATCH*HEADS, NSPLIT), 256>>>(qkv, Apb);
        areduce_kernel<<<(BATCH*HEADS*DHEAD*DHEAD/4)/256, 256>>>(Apb, Ab);
        attnO_kernel<<<dim3(HEADS, BATCH, SEQ/128), 256>>>(qkv, Ab, oh, ol);
        // h = h + o Wo^T + bo  (fp32 residual, writes fp32 h + splits)
        tc_gemm<3><<<gD, 256, SMEM_GEMM>>>(oh, ol, woh+oD, wol+oD, bol, h,
                                           h, hh, hl, NTOK, DIM, DIM);
        // f = relu(h W1^T + b1)  (splits)
        tc_gemm<1><<<gFF, 256, SMEM_GEMM>>>(hh, hl, w1h+oF, w1l+oF, b1l, nullptr,
                                            nullptr, fh, fl, NTOK, FFD, DIM);
        // t = h + f W2^T + b2  (fp32 residual, fp32 out for LN)
        tc_gemm<2><<<gD, 256, SMEM_GEMM>>>(fh, fl, w2h+oF, w2l+oF, b2l, h,
                                           tb, nullptr, nullptr, NTOK, DIM, FFD);
        // h = LN(t)  (fp32 h + splits), 2 rows per block
        ln_kernel<<<NTOK/2, 256>>>(tb, g2l, be2l, h, hh, hl);
    }

    // logits, written directly transposed into d_out [B, V, S]
    tc_gemm<4><<<gV, 256, SMEM_GEMM>>>(hh, hl, wfh, wfl, bfc, nullptr,
                                       (float*)d_out, nullptr, nullptr, NTOK, VOC, DIM);
}